// round 7
// baseline (speedup 1.0000x reference)
#include <cuda_runtime.h>
#include <cuda_bf16.h>
#include <math.h>

// ---------------- problem constants ----------------
#define BSZ   32
#define CCH   256
#define NPIX  4096      // 64x64

// ---------------- scratch (device globals; no allocation) ----------------
__device__ __align__(16) __nv_bfloat16  g_yh[(size_t)BSZ * CCH * NPIX];   // conv out hi
__device__ __align__(16) __nv_bfloat16  g_yl[(size_t)BSZ * CCH * NPIX];   // conv out lo
__device__ __align__(16) __nv_bfloat16  g_xt_hi[(size_t)BSZ * NPIX * CCH];
__device__ __align__(16) __nv_bfloat16  g_xt_lo[(size_t)BSZ * NPIX * CCH];
__device__ __align__(16) __nv_bfloat16  g_wa_hi[9 * CCH * CCH];
__device__ __align__(16) __nv_bfloat16  g_wa_lo[9 * CCH * CCH];
__device__ float                        g_ginv[2 * CCH * 64];
__device__ __align__(16) __nv_bfloat16  g_gyT_hi[CCH * 4096];  // GyT[c][j][q]
__device__ __align__(16) __nv_bfloat16  g_gyT_lo[CCH * 4096];
__device__ __align__(16) __nv_bfloat16  g_gx_hi[CCH * 4096];   // Gx[c][i][h]
__device__ __align__(16) __nv_bfloat16  g_gx_lo[CCH * 4096];

// ---------------- helpers ----------------
__device__ __forceinline__ unsigned smem_u32(const void* p) {
    unsigned r;
    asm("{ .reg .u64 t; cvta.to.shared.u64 t, %1; cvt.u32.u64 %0, t; }" : "=r"(r) : "l"(p));
    return r;
}
__device__ __forceinline__ unsigned sw128(unsigned off) { return off ^ ((off >> 3) & 0x70); }

__device__ __forceinline__ void ldm_x4(unsigned* r, unsigned addr) {
    asm volatile("ldmatrix.sync.aligned.m8n8.x4.shared.b16 {%0,%1,%2,%3}, [%4];"
        : "=r"(r[0]), "=r"(r[1]), "=r"(r[2]), "=r"(r[3]) : "r"(addr));
}
__device__ __forceinline__ void mma16816(float* d, const unsigned* a,
                                         unsigned b0, unsigned b1) {
    asm volatile("mma.sync.aligned.m16n8k16.row.col.f32.bf16.bf16.f32 "
        "{%0,%1,%2,%3}, {%4,%5,%6,%7}, {%8,%9}, {%0,%1,%2,%3};"
        : "+f"(d[0]), "+f"(d[1]), "+f"(d[2]), "+f"(d[3])
        : "r"(a[0]), "r"(a[1]), "r"(a[2]), "r"(a[3]), "r"(b0), "r"(b1));
}
__device__ __forceinline__ void cp16(unsigned dst, const void* src) {
    asm volatile("cp.async.cg.shared.global [%0], [%1], 16;" :: "r"(dst), "l"(src));
}
__device__ __forceinline__ void cp16z(unsigned dst, const void* src, bool ok) {
    int sz = ok ? 16 : 0;
    asm volatile("cp.async.cg.shared.global [%0], [%1], 16, %2;"
                 :: "r"(dst), "l"(src), "r"(sz));
}
__device__ __forceinline__ void cp_commit() {
    asm volatile("cp.async.commit_group;" ::: "memory");
}
__device__ __forceinline__ void cp_wait0() {
    asm volatile("cp.async.wait_group 0;" ::: "memory");
}
// split a float pair into packed bf16x2 hi + lo words
__device__ __forceinline__ void split2(float a, float b, unsigned& uh, unsigned& ul) {
    __nv_bfloat16 ha = __float2bfloat16(a), hb = __float2bfloat16(b);
    float ra = a - __bfloat162float(ha), rb = b - __bfloat162float(hb);
    __nv_bfloat16 la = __float2bfloat16(ra), lb = __float2bfloat16(rb);
    uh = (unsigned)__bfloat16_as_ushort(ha) | ((unsigned)__bfloat16_as_ushort(hb) << 16);
    ul = (unsigned)__bfloat16_as_ushort(la) | ((unsigned)__bfloat16_as_ushort(lb) << 16);
}

// ---------------- kernel 1: weights -> [tap][co][ci] bf16 hi/lo ----------------
// one CTA per co; smem transpose, 16B vectorized stores
__global__ void wa_kernel(const float* __restrict__ w) {
    __shared__ float s[2304];
    const int co  = blockIdx.x;
    const int tid = threadIdx.x;
    for (int i = tid; i < 2304; i += 256) s[i] = w[(size_t)co * 2304 + i];
    __syncthreads();
    for (int it = tid; it < 288; it += 256) {   // 9 taps x 32 ci-groups
        int tap = it >> 5, grp = it & 31;
        unsigned h4[4], l4[4];
        #pragma unroll
        for (int k = 0; k < 4; k++) {
            float a = s[(grp * 8 + k * 2) * 9 + tap];
            float b = s[(grp * 8 + k * 2 + 1) * 9 + tap];
            split2(a, b, h4[k], l4[k]);
        }
        size_t o = ((size_t)tap * 256 + co) * 256 + grp * 8;
        *(uint4*)(g_wa_hi + o) = make_uint4(h4[0], h4[1], h4[2], h4[3]);
        *(uint4*)(g_wa_lo + o) = make_uint4(l4[0], l4[1], l4[2], l4[3]);
    }
}

// ---------------- kernel 2: x -> transposed bf16 hi/lo (16B stores) ----------------
__global__ void xt_kernel(const float* __restrict__ x) {
    __shared__ float s[64][65];
    int p0  = blockIdx.x * 64;
    int ci0 = blockIdx.y * 64;
    int b   = blockIdx.z;
    int tid = threadIdx.x;
    for (int i = tid; i < 4096; i += 256) {
        int ci = i >> 6, p = i & 63;
        s[ci][p] = x[((size_t)(b * 256 + ci0 + ci)) * NPIX + p0 + p];
    }
    __syncthreads();
    for (int i = tid; i < 512; i += 256) {      // 64 pix x 8 ci-groups
        int pix = i >> 3, grp = i & 7;
        unsigned h4[4], l4[4];
        #pragma unroll
        for (int k = 0; k < 4; k++) {
            float a = s[grp * 8 + k * 2][pix];
            float bq = s[grp * 8 + k * 2 + 1][pix];
            split2(a, bq, h4[k], l4[k]);
        }
        size_t o = ((size_t)b * NPIX + p0 + pix) * 256 + ci0 + grp * 8;
        *(uint4*)(g_xt_hi + o) = make_uint4(h4[0], h4[1], h4[2], h4[3]);
        *(uint4*)(g_xt_lo + o) = make_uint4(l4[0], l4[1], l4[2], l4[3]);
    }
}

// ---------------- kernel 3: circulant inverse kernels ----------------
__global__ void ginv_kernel(const float* __restrict__ alpha) {
    int c = blockIdx.x;
    int t = threadIdx.x;
    int dir = t >> 6;
    int n   = t & 63;
    float t00 = tanhf(alpha[c*4+0]), t01 = tanhf(alpha[c*4+1]);
    float t10 = tanhf(alpha[c*4+2]), t11 = tanhf(alpha[c*4+3]);
    const float R = 0.70710678118654752440f;
    float a0, a2;
    if (dir == 0) { a0 = (t00 + t01) * R; a2 = (t01 - t00) * R; }
    else          { a0 = (t10 + t11) * R; a2 = (t11 - t10) * R; }
    double ar = (double)a0 + (double)a2;
    double ai = (double)a0 - (double)a2;
    double s = 0.0;
    for (int u = 0; u < 64; u++) {
        double th  = (2.0 * 3.14159265358979323846 / 64.0) * (double)u;
        double Fre = 1.0 + ar * cos(th);
        double Fim = ai * sin(th);
        double den = Fre * Fre + Fim * Fim;
        double ang = th * (double)n;
        s += (cos(ang) * Fre + sin(ang) * Fim) / den;
    }
    g_ginv[(dir * CCH + c) * 64 + n] = (float)(s / 64.0);
}

// ---------------- kernel 3b: circulant matrices (bf16 hi/lo, 16B stores) ----------------
__global__ void gmat_kernel() {
    int c   = blockIdx.x;
    int tid = threadIdx.x;
    __shared__ float gx[64], gy[64];
    if (tid < 64)                 gx[tid]      = g_ginv[c * 64 + tid];
    else if (tid < 128)           gy[tid - 64] = g_ginv[(CCH + c) * 64 + (tid - 64)];
    __syncthreads();
    for (int i = tid; i < 512; i += 256) {      // 64 rows x 8 q-groups
        int r = i >> 3, grp = i & 7;
        unsigned xh4[4], xl4[4], yh4[4], yl4[4];
        #pragma unroll
        for (int k = 0; k < 4; k++) {
            int q0 = grp * 8 + k * 2;
            split2(gx[(r - q0) & 63], gx[(r - q0 - 1) & 63], xh4[k], xl4[k]);
            split2(gy[(r - q0) & 63], gy[(r - q0 - 1) & 63], yh4[k], yl4[k]);
        }
        size_t o = (size_t)c * 4096 + r * 64 + grp * 8;
        *(uint4*)(g_gx_hi  + o) = make_uint4(xh4[0], xh4[1], xh4[2], xh4[3]);
        *(uint4*)(g_gx_lo  + o) = make_uint4(xl4[0], xl4[1], xl4[2], xl4[3]);
        *(uint4*)(g_gyT_hi + o) = make_uint4(yh4[0], yh4[1], yh4[2], yh4[3]);
        *(uint4*)(g_gyT_lo + o) = make_uint4(yl4[0], yl4[1], yl4[2], yl4[3]);
    }
}

// ---------------- kernel 4: implicit-GEMM conv via mma.sync (unchanged) ----------------
#define XPAT_ROWS  (6 * 68)
#define XPAT_BYTES (XPAT_ROWS * 128)   // 52224
#define OFF_XH 0u
#define OFF_XL (OFF_XH + XPAT_BYTES)
#define OFF_A0 (OFF_XL + XPAT_BYTES)
#define A_BUF  32768u
#define A_LO   16384u
#define CONV_SMEM (OFF_A0 + 2 * A_BUF) // 169984

__global__ __launch_bounds__(256, 1)
void conv_mma_kernel() {
    extern __shared__ char smem[];
    const unsigned sb = smem_u32(smem);
    const int tid = threadIdx.x;
    const int lid = tid & 31;
    const int wid = tid >> 5;
    const int wm  = wid & 1;
    const int wn  = wid >> 1;

    const int n0  = blockIdx.x * 256;
    const int h0  = n0 >> 6;
    const int co0 = blockIdx.y * 128;
    const int b   = blockIdx.z;

    const __nv_bfloat16* xh = g_xt_hi + (size_t)b * NPIX * 256;
    const __nv_bfloat16* xl = g_xt_lo + (size_t)b * NPIX * 256;

    float acc[4][8][4];
    #pragma unroll
    for (int mt = 0; mt < 4; mt++)
        #pragma unroll
        for (int nt = 0; nt < 8; nt++)
            #pragma unroll
            for (int k = 0; k < 4; k++) acc[mt][nt][k] = 0.f;

    unsigned a_rowoff[4];
    #pragma unroll
    for (int mt = 0; mt < 4; mt++) {
        int row = wm * 64 + mt * 16 + (lid & 7) + ((lid >> 3) & 1) * 8;
        a_rowoff[mt] = (unsigned)(row * 128) + ((unsigned)(lid >> 4)) * 16u;
    }
    int bn[4];
    #pragma unroll
    for (int j = 0; j < 4; j++) bn[j] = wn * 64 + j * 16 + (lid & 15);
    const unsigned bk8 = ((unsigned)(lid >> 4)) * 16u;

    auto stageA = [&](int tap, int ci0, int s) {
        unsigned dH = sb + OFF_A0 + (unsigned)s * A_BUF;
        unsigned dL = dH + A_LO;
        #pragma unroll
        for (int i = tid; i < 1024; i += 256) {
            int cq = i & 7, row = i >> 3;
            size_t src = ((size_t)tap * 256 + co0 + row) * 256 + ci0 + cq * 8;
            unsigned swo = sw128((unsigned)(row * 128 + cq * 16));
            cp16(dH + swo, g_wa_hi + src);
            cp16(dL + swo, g_wa_lo + src);
        }
        cp_commit();
    };

    for (int cc = 0; cc < 4; cc++) {
        const int ci0 = cc << 6;
        __syncthreads();
        for (int i = tid; i < 6 * 66 * 8; i += 256) {
            int cq  = i & 7;
            int row = i >> 3;
            int hl  = row / 66;
            int wv  = row - hl * 66;
            int h = h0 + hl - 1;
            int w = wv - 1;
            bool ok = ((unsigned)h < 64u) && ((unsigned)w < 64u);
            size_t src = ok ? (((size_t)(h * 64 + w)) * 256 + ci0 + cq * 8) : 0;
            unsigned swo = sw128((unsigned)((hl * 68 + wv) * 128 + cq * 16));
            cp16z(sb + OFF_XH + swo, xh + src, ok);
            cp16z(sb + OFF_XL + swo, xl + src, ok);
        }
        stageA(0, ci0, 0);
        cp_wait0();
        __syncthreads();

        for (int tap = 0; tap < 9; tap++) {
            const int s  = tap & 1;
            const int dh = tap / 3 - 1;
            const int dw = tap % 3 - 1;
            if (tap < 8) stageA(tap + 1, ci0, s ^ 1);

            const unsigned AH = sb + OFF_A0 + (unsigned)s * A_BUF;
            const unsigned AL = AH + A_LO;

            unsigned b_rowoff[4];
            #pragma unroll
            for (int j = 0; j < 4; j++) {
                int hl = bn[j] >> 6, w = bn[j] & 63;
                b_rowoff[j] = (unsigned)(((hl + dh + 1) * 68 + (w + dw + 1)) * 128) + bk8;
            }

            #pragma unroll
            for (int ks = 0; ks < 4; ks++) {
                unsigned afH[4][4], afL[4][4], bfH[4][4], bfL[4][4];
                #pragma unroll
                for (int mt = 0; mt < 4; mt++)
                    ldm_x4(afH[mt], AH + sw128(a_rowoff[mt] + ks * 32u));
                #pragma unroll
                for (int j = 0; j < 4; j++)
                    ldm_x4(bfH[j], sb + OFF_XH + sw128(b_rowoff[j] + ks * 32u));
                #pragma unroll
                for (int mt = 0; mt < 4; mt++)
                    #pragma unroll
                    for (int nt = 0; nt < 8; nt++)
                        mma16816(acc[mt][nt], afH[mt],
                                 bfH[nt >> 1][nt & 1], bfH[nt >> 1][(nt & 1) + 2]);
                #pragma unroll
                for (int j = 0; j < 4; j++)
                    ldm_x4(bfL[j], sb + OFF_XL + sw128(b_rowoff[j] + ks * 32u));
                #pragma unroll
                for (int mt = 0; mt < 4; mt++)
                    #pragma unroll
                    for (int nt = 0; nt < 8; nt++)
                        mma16816(acc[mt][nt], afH[mt],
                                 bfL[nt >> 1][nt & 1], bfL[nt >> 1][(nt & 1) + 2]);
                #pragma unroll
                for (int mt = 0; mt < 4; mt++)
                    ldm_x4(afL[mt], AL + sw128(a_rowoff[mt] + ks * 32u));
                #pragma unroll
                for (int mt = 0; mt < 4; mt++)
                    #pragma unroll
                    for (int nt = 0; nt < 8; nt++)
                        mma16816(acc[mt][nt], afL[mt],
                                 bfH[nt >> 1][nt & 1], bfH[nt >> 1][(nt & 1) + 2]);
            }
            if (tap < 8) {
                cp_wait0();
                __syncthreads();
            }
        }
    }

    const int r4 = lid >> 2, c2 = (lid & 3) << 1;
    #pragma unroll
    for (int mt = 0; mt < 4; mt++) {
        #pragma unroll
        for (int nt = 0; nt < 8; nt++) {
            int co  = co0 + wm * 64 + mt * 16 + r4;
            int pix = n0 + wn * 64 + nt * 8 + c2;
            size_t base = ((size_t)(b * 256 + co)) * NPIX + pix;
            unsigned uh, ul;
            split2(acc[mt][nt][0], acc[mt][nt][1], uh, ul);
            *(unsigned*)(g_yh + base) = uh;
            *(unsigned*)(g_yl + base) = ul;
            split2(acc[mt][nt][2], acc[mt][nt][3], uh, ul);
            *(unsigned*)(g_yh + base + (size_t)8 * NPIX) = uh;
            *(unsigned*)(g_yl + base + (size_t)8 * NPIX) = ul;
        }
    }
}

// ---------------- kernel 5: ARMA solve, 2 slices (same channel) per CTA ----------------
// slices: (2*bg)*256+c and (2*bg+1)*256+c share Gx/GyT.
// stage 1: UT[s*64+j][h] = sum_q GyT[j][q] * Y_s[h][q]   (A=GyT, B rows = s*64+h)
// stage 2: out_s[i][j]   = sum_h Gx[i][h]  * UT[s*64+j][h]
// UT overwrites the Y region after a sync. 96 KB smem -> 2 CTAs/SM.
#define PA_BYH 0u
#define PA_BYL 32768u
#define PA_GYH 65536u
#define PA_GYL 73728u
#define PA_GXH 81920u
#define PA_GXL 90112u
#define ARMA_SMEM 98304

__global__ __launch_bounds__(128, 2)
void arma_mma_kernel(float* __restrict__ out) {
    extern __shared__ char smem[];
    const unsigned sb = smem_u32(smem);
    const int tid = threadIdx.x;
    const int lid = tid & 31;
    const int wid = tid >> 5;
    const int c   = blockIdx.x & 255;
    const int bg  = blockIdx.x >> 8;
    const int slice0 = (2 * bg) * 256 + c;     // second slice = slice0 + 256

    // ---- stage inputs ----
    for (int i = tid; i < 2048; i += 128) {    // 256 rows (2 slices x 64 h) x 8 grp
        int r = i >> 3, cq = i & 7;
        int s = r >> 6, h = r & 63;
        size_t e = ((size_t)(slice0 + s * 256)) * 4096 + h * 64 + cq * 8;
        unsigned swo = sw128((unsigned)(r * 128 + cq * 16));
        cp16(sb + PA_BYH + swo, g_yh + e);
        cp16(sb + PA_BYL + swo, g_yl + e);
    }
    for (int i = tid; i < 512; i += 128) {     // 64 rows x 8 grp
        int r = i >> 3, cq = i & 7;
        size_t e = (size_t)c * 4096 + r * 64 + cq * 8;
        unsigned swo = sw128((unsigned)(r * 128 + cq * 16));
        cp16(sb + PA_GYH + swo, g_gyT_hi + e);
        cp16(sb + PA_GYL + swo, g_gyT_lo + e);
        cp16(sb + PA_GXH + swo, g_gx_hi  + e);
        cp16(sb + PA_GXL + swo, g_gx_lo  + e);
    }
    cp_commit(); cp_wait0();
    __syncthreads();

    // warp layout: 4 warps = 2M x 2N; warp tile M=32 (mt=2), N=64 (nt=8)
    const int wm = wid & 1, wn = wid >> 1;
    unsigned a_rowoff[2];
    #pragma unroll
    for (int mt = 0; mt < 2; mt++) {
        int row = wm * 32 + mt * 16 + (lid & 7) + ((lid >> 3) & 1) * 8;
        a_rowoff[mt] = (unsigned)(row * 128) + ((unsigned)(lid >> 4)) * 16u;
    }
    unsigned b_off[4];
    #pragma unroll
    for (int j = 0; j < 4; j++)
        b_off[j] = (unsigned)((wn * 64 + j * 16 + (lid & 15)) * 128)
                 + ((unsigned)(lid >> 4)) * 16u;
    const int r4 = lid >> 2, cp2 = (lid & 3) << 1;

    // ---- stage 1 ----
    float acc[2][8][4];
    #pragma unroll
    for (int mt = 0; mt < 2; mt++)
        #pragma unroll
        for (int nt = 0; nt < 8; nt++)
            #pragma unroll
            for (int k = 0; k < 4; k++) acc[mt][nt][k] = 0.f;

    #pragma unroll
    for (int ks = 0; ks < 4; ks++) {
        unsigned AH[2][4], AL[2][4], BH[4][4], BL[4][4];
        #pragma unroll
        for (int mt = 0; mt < 2; mt++) {
            ldm_x4(AH[mt], sb + PA_GYH + sw128(a_rowoff[mt] + ks * 32u));
            ldm_x4(AL[mt], sb + PA_GYL + sw128(a_rowoff[mt] + ks * 32u));
        }
        #pragma unroll
        for (int j = 0; j < 4; j++) {
            ldm_x4(BH[j], sb + PA_BYH + sw128(b_off[j] + ks * 32u));
            ldm_x4(BL[j], sb + PA_BYL + sw128(b_off[j] + ks * 32u));
        }
        #pragma unroll
        for (int mt = 0; mt < 2; mt++)
            #pragma unroll
            for (int nt = 0; nt < 8; nt++) {
                unsigned h0b = BH[nt >> 1][nt & 1], h1b = BH[nt >> 1][(nt & 1) + 2];
                mma16816(acc[mt][nt], AH[mt], h0b, h1b);
                mma16816(acc[mt][nt], AH[mt],
                         BL[nt >> 1][nt & 1], BL[nt >> 1][(nt & 1) + 2]);
                mma16816(acc[mt][nt], AL[mt], h0b, h1b);
            }
    }
    __syncthreads();   // all BY reads complete before overwrite

    // write UT (row = s*64 + j, col = h) into BY region as bf16 hi/lo
    #pragma unroll
    for (int mt = 0; mt < 2; mt++) {
        #pragma unroll
        for (int nt = 0; nt < 8; nt++) {
            int m = wm * 32 + mt * 16 + r4;
            int n = wn * 64 + nt * 8 + cp2;
            int row = (n & ~63) + m;
            int col = n & 63;
            unsigned uh, ul;
            split2(acc[mt][nt][0], acc[mt][nt][1], uh, ul);
            unsigned ad = sw128((unsigned)(row * 128 + col * 2));
            *(unsigned*)(smem + PA_BYH + ad) = uh;
            *(unsigned*)(smem + PA_BYL + ad) = ul;
            split2(acc[mt][nt][2], acc[mt][nt][3], uh, ul);
            ad = sw128((unsigned)((row + 8) * 128 + col * 2));
            *(unsigned*)(smem + PA_BYH + ad) = uh;
            *(unsigned*)(smem + PA_BYL + ad) = ul;
        }
    }
    __syncthreads();

    // ---- stage 2 ----
    float o[2][8][4];
    #pragma unroll
    for (int mt = 0; mt < 2; mt++)
        #pragma unroll
        for (int nt = 0; nt < 8; nt++)
            #pragma unroll
            for (int k = 0; k < 4; k++) o[mt][nt][k] = 0.f;

    #pragma unroll
    for (int ks = 0; ks < 4; ks++) {
        unsigned AH[2][4], AL[2][4], BH[4][4], BL[4][4];
        #pragma unroll
        for (int mt = 0; mt < 2; mt++) {
            ldm_x4(AH[mt], sb + PA_GXH + sw128(a_rowoff[mt] + ks * 32u));
            ldm_x4(AL[mt], sb + PA_GXL + sw128(a_rowoff[mt] + ks * 32u));
        }
        #pragma unroll
        for (int j = 0; j < 4; j++) {
            ldm_x4(BH[j], sb + PA_BYH + sw128(b_off[j] + ks * 32u));
            ldm_x4(BL[j], sb + PA_BYL + sw128(b_off[j] + ks * 32u));
        }
        #pragma unroll
        for (int mt = 0; mt < 2; mt++)
            #pragma unroll
            for (int nt = 0; nt < 8; nt++) {
                unsigned h0b = BH[nt >> 1][nt & 1], h1b = BH[nt >> 1][(nt & 1) + 2];
                mma16816(o[mt][nt], AH[mt], h0b, h1b);
                mma16816(o[mt][nt], AH[mt],
                         BL[nt >> 1][nt & 1], BL[nt >> 1][(nt & 1) + 2]);
                mma16816(o[mt][nt], AL[mt], h0b, h1b);
            }
    }

    // epilogue: out_s[i][j]; fragment (m=i, n=s*64+j)
    #pragma unroll
    for (int mt = 0; mt < 2; mt++) {
        #pragma unroll
        for (int nt = 0; nt < 8; nt++) {
            int m = wm * 32 + mt * 16 + r4;
            int n = wn * 64 + nt * 8 + cp2;
            int s = n >> 6;
            int j = n & 63;
            float* O = out + ((size_t)(slice0 + s * 256)) * 4096;
            *(float2*)(O + m * 64 + j)       = make_float2(o[mt][nt][0], o[mt][nt][1]);
            *(float2*)(O + (m + 8) * 64 + j) = make_float2(o[mt][nt][2], o[mt][nt][3]);
        }
    }
}

// ---------------- launcher ----------------
extern "C" void kernel_launch(void* const* d_in, const int* in_sizes, int n_in,
                              void* d_out, int out_size) {
    const float* x     = (const float*)d_in[0];
    const float* w     = (const float*)d_in[1];
    const float* alpha = (const float*)d_in[2];
    float* out = (float*)d_out;

    cudaFuncSetAttribute(conv_mma_kernel,
                         cudaFuncAttributeMaxDynamicSharedMemorySize, CONV_SMEM);
    cudaFuncSetAttribute(arma_mma_kernel,
                         cudaFuncAttributeMaxDynamicSharedMemorySize, ARMA_SMEM);

    wa_kernel<<<CCH, 256>>>(w);
    ginv_kernel<<<CCH, 128>>>(alpha);
    gmat_kernel<<<CCH, 256>>>();
    xt_kernel<<<dim3(64, 4, 32), 256>>>(x);
    conv_mma_kernel<<<dim3(16, 2, 32), 256, CONV_SMEM>>>();
    arma_mma_kernel<<<16 * 256, 128, ARMA_SMEM>>>(out);
}

// round 8
// speedup vs baseline: 1.0124x; 1.0124x over previous
#include <cuda_runtime.h>
#include <cuda_bf16.h>
#include <math.h>

// ---------------- problem constants ----------------
#define BSZ   32
#define CCH   256
#define NPIX  4096      // 64x64

// ---------------- scratch (device globals; no allocation) ----------------
__device__ __align__(16) __nv_bfloat16  g_yh[(size_t)BSZ * CCH * NPIX];   // conv out hi
__device__ __align__(16) __nv_bfloat16  g_yl[(size_t)BSZ * CCH * NPIX];   // conv out lo
__device__ __align__(16) __nv_bfloat16  g_xt_hi[(size_t)BSZ * NPIX * CCH];
__device__ __align__(16) __nv_bfloat16  g_xt_lo[(size_t)BSZ * NPIX * CCH];
__device__ __align__(16) __nv_bfloat16  g_wa_hi[9 * CCH * CCH];
__device__ __align__(16) __nv_bfloat16  g_wa_lo[9 * CCH * CCH];
__device__ float                        g_ginv[2 * CCH * 64];
__device__ __align__(16) __nv_bfloat16  g_gyT_hi[CCH * 4096];  // GyT[c][j][q]
__device__ __align__(16) __nv_bfloat16  g_gyT_lo[CCH * 4096];
__device__ __align__(16) __nv_bfloat16  g_gx_hi[CCH * 4096];   // Gx[c][i][h]
__device__ __align__(16) __nv_bfloat16  g_gx_lo[CCH * 4096];

// ---------------- helpers ----------------
__device__ __forceinline__ unsigned smem_u32(const void* p) {
    unsigned r;
    asm("{ .reg .u64 t; cvta.to.shared.u64 t, %1; cvt.u32.u64 %0, t; }" : "=r"(r) : "l"(p));
    return r;
}
__device__ __forceinline__ unsigned sw128(unsigned off) { return off ^ ((off >> 3) & 0x70); }

__device__ __forceinline__ void ldm_x4(unsigned* r, unsigned addr) {
    asm volatile("ldmatrix.sync.aligned.m8n8.x4.shared.b16 {%0,%1,%2,%3}, [%4];"
        : "=r"(r[0]), "=r"(r[1]), "=r"(r[2]), "=r"(r[3]) : "r"(addr));
}
__device__ __forceinline__ void mma16816(float* d, const unsigned* a,
                                         unsigned b0, unsigned b1) {
    asm volatile("mma.sync.aligned.m16n8k16.row.col.f32.bf16.bf16.f32 "
        "{%0,%1,%2,%3}, {%4,%5,%6,%7}, {%8,%9}, {%0,%1,%2,%3};"
        : "+f"(d[0]), "+f"(d[1]), "+f"(d[2]), "+f"(d[3])
        : "r"(a[0]), "r"(a[1]), "r"(a[2]), "r"(a[3]), "r"(b0), "r"(b1));
}
__device__ __forceinline__ void cp16(unsigned dst, const void* src) {
    asm volatile("cp.async.cg.shared.global [%0], [%1], 16;" :: "r"(dst), "l"(src));
}
__device__ __forceinline__ void cp16z(unsigned dst, const void* src, bool ok) {
    int sz = ok ? 16 : 0;
    asm volatile("cp.async.cg.shared.global [%0], [%1], 16, %2;"
                 :: "r"(dst), "l"(src), "r"(sz));
}
__device__ __forceinline__ void cp_commit() {
    asm volatile("cp.async.commit_group;" ::: "memory");
}
__device__ __forceinline__ void cp_wait0() {
    asm volatile("cp.async.wait_group 0;" ::: "memory");
}
// split a float pair into packed bf16x2 hi + lo words
__device__ __forceinline__ void split2(float a, float b, unsigned& uh, unsigned& ul) {
    __nv_bfloat16 ha = __float2bfloat16(a), hb = __float2bfloat16(b);
    float ra = a - __bfloat162float(ha), rb = b - __bfloat162float(hb);
    __nv_bfloat16 la = __float2bfloat16(ra), lb = __float2bfloat16(rb);
    uh = (unsigned)__bfloat16_as_ushort(ha) | ((unsigned)__bfloat16_as_ushort(hb) << 16);
    ul = (unsigned)__bfloat16_as_ushort(la) | ((unsigned)__bfloat16_as_ushort(lb) << 16);
}

// ---------------- kernel 1: weights -> [tap][co][ci] bf16 hi/lo ----------------
__global__ void wa_kernel(const float* __restrict__ w) {
    __shared__ float s[2304];
    const int co  = blockIdx.x;
    const int tid = threadIdx.x;
    for (int i = tid; i < 2304; i += 256) s[i] = w[(size_t)co * 2304 + i];
    __syncthreads();
    for (int it = tid; it < 288; it += 256) {   // 9 taps x 32 ci-groups
        int tap = it >> 5, grp = it & 31;
        unsigned h4[4], l4[4];
        #pragma unroll
        for (int k = 0; k < 4; k++) {
            float a = s[(grp * 8 + k * 2) * 9 + tap];
            float b = s[(grp * 8 + k * 2 + 1) * 9 + tap];
            split2(a, b, h4[k], l4[k]);
        }
        size_t o = ((size_t)tap * 256 + co) * 256 + grp * 8;
        *(uint4*)(g_wa_hi + o) = make_uint4(h4[0], h4[1], h4[2], h4[3]);
        *(uint4*)(g_wa_lo + o) = make_uint4(l4[0], l4[1], l4[2], l4[3]);
    }
}

// ---------------- kernel 2: x -> transposed bf16 hi/lo (16B stores) ----------------
__global__ void xt_kernel(const float* __restrict__ x) {
    __shared__ float s[64][65];
    int p0  = blockIdx.x * 64;
    int ci0 = blockIdx.y * 64;
    int b   = blockIdx.z;
    int tid = threadIdx.x;
    for (int i = tid; i < 4096; i += 256) {
        int ci = i >> 6, p = i & 63;
        s[ci][p] = x[((size_t)(b * 256 + ci0 + ci)) * NPIX + p0 + p];
    }
    __syncthreads();
    for (int i = tid; i < 512; i += 256) {      // 64 pix x 8 ci-groups
        int pix = i >> 3, grp = i & 7;
        unsigned h4[4], l4[4];
        #pragma unroll
        for (int k = 0; k < 4; k++) {
            float a = s[grp * 8 + k * 2][pix];
            float bq = s[grp * 8 + k * 2 + 1][pix];
            split2(a, bq, h4[k], l4[k]);
        }
        size_t o = ((size_t)b * NPIX + p0 + pix) * 256 + ci0 + grp * 8;
        *(uint4*)(g_xt_hi + o) = make_uint4(h4[0], h4[1], h4[2], h4[3]);
        *(uint4*)(g_xt_lo + o) = make_uint4(l4[0], l4[1], l4[2], l4[3]);
    }
}

// ---------------- kernel 3: circulant inverse kernels ----------------
__global__ void ginv_kernel(const float* __restrict__ alpha) {
    int c = blockIdx.x;
    int t = threadIdx.x;
    int dir = t >> 6;
    int n   = t & 63;
    float t00 = tanhf(alpha[c*4+0]), t01 = tanhf(alpha[c*4+1]);
    float t10 = tanhf(alpha[c*4+2]), t11 = tanhf(alpha[c*4+3]);
    const float R = 0.70710678118654752440f;
    float a0, a2;
    if (dir == 0) { a0 = (t00 + t01) * R; a2 = (t01 - t00) * R; }
    else          { a0 = (t10 + t11) * R; a2 = (t11 - t10) * R; }
    double ar = (double)a0 + (double)a2;
    double ai = (double)a0 - (double)a2;
    double s = 0.0;
    for (int u = 0; u < 64; u++) {
        double th  = (2.0 * 3.14159265358979323846 / 64.0) * (double)u;
        double Fre = 1.0 + ar * cos(th);
        double Fim = ai * sin(th);
        double den = Fre * Fre + Fim * Fim;
        double ang = th * (double)n;
        s += (cos(ang) * Fre + sin(ang) * Fim) / den;
    }
    g_ginv[(dir * CCH + c) * 64 + n] = (float)(s / 64.0);
}

// ---------------- kernel 3b: circulant matrices (bf16 hi/lo, 16B stores) ----------------
__global__ void gmat_kernel() {
    int c   = blockIdx.x;
    int tid = threadIdx.x;
    __shared__ float gx[64], gy[64];
    if (tid < 64)                 gx[tid]      = g_ginv[c * 64 + tid];
    else if (tid < 128)           gy[tid - 64] = g_ginv[(CCH + c) * 64 + (tid - 64)];
    __syncthreads();
    for (int i = tid; i < 512; i += 256) {      // 64 rows x 8 q-groups
        int r = i >> 3, grp = i & 7;
        unsigned xh4[4], xl4[4], yh4[4], yl4[4];
        #pragma unroll
        for (int k = 0; k < 4; k++) {
            int q0 = grp * 8 + k * 2;
            split2(gx[(r - q0) & 63], gx[(r - q0 - 1) & 63], xh4[k], xl4[k]);
            split2(gy[(r - q0) & 63], gy[(r - q0 - 1) & 63], yh4[k], yl4[k]);
        }
        size_t o = (size_t)c * 4096 + r * 64 + grp * 8;
        *(uint4*)(g_gx_hi  + o) = make_uint4(xh4[0], xh4[1], xh4[2], xh4[3]);
        *(uint4*)(g_gx_lo  + o) = make_uint4(xl4[0], xl4[1], xl4[2], xl4[3]);
        *(uint4*)(g_gyT_hi + o) = make_uint4(yh4[0], yh4[1], yh4[2], yh4[3]);
        *(uint4*)(g_gyT_lo + o) = make_uint4(yl4[0], yl4[1], yl4[2], yl4[3]);
    }
}

// ---------------- kernel 4: implicit-GEMM conv via mma.sync ----------------
// CTA: M=128 co x N=256 pixels. 512 threads = 16 warps (4M x 4N), warp tile 32x64.
// Inner-loop term order HH -> LH -> HL to cap register liveness at 128/thread.
#define XPAT_ROWS  (6 * 68)
#define XPAT_BYTES (XPAT_ROWS * 128)   // 52224
#define OFF_XH 0u
#define OFF_XL (OFF_XH + XPAT_BYTES)
#define OFF_A0 (OFF_XL + XPAT_BYTES)
#define A_BUF  32768u
#define A_LO   16384u
#define CONV_SMEM (OFF_A0 + 2 * A_BUF) // 169984

__global__ __launch_bounds__(512, 1)
void conv_mma_kernel() {
    extern __shared__ char smem[];
    const unsigned sb = smem_u32(smem);
    const int tid = threadIdx.x;
    const int lid = tid & 31;
    const int wid = tid >> 5;
    const int wm  = wid & 3;            // 0..3 (32 co each)
    const int wn  = wid >> 2;           // 0..3 (64 pixels each)

    const int n0  = blockIdx.x * 256;
    const int h0  = n0 >> 6;
    const int co0 = blockIdx.y * 128;
    const int b   = blockIdx.z;

    const __nv_bfloat16* xh = g_xt_hi + (size_t)b * NPIX * 256;
    const __nv_bfloat16* xl = g_xt_lo + (size_t)b * NPIX * 256;

    float acc[2][8][4];
    #pragma unroll
    for (int mt = 0; mt < 2; mt++)
        #pragma unroll
        for (int nt = 0; nt < 8; nt++)
            #pragma unroll
            for (int k = 0; k < 4; k++) acc[mt][nt][k] = 0.f;

    unsigned a_rowoff[2];
    #pragma unroll
    for (int mt = 0; mt < 2; mt++) {
        int row = wm * 32 + mt * 16 + (lid & 7) + ((lid >> 3) & 1) * 8;
        a_rowoff[mt] = (unsigned)(row * 128) + ((unsigned)(lid >> 4)) * 16u;
    }
    int bn[4];
    #pragma unroll
    for (int j = 0; j < 4; j++) bn[j] = wn * 64 + j * 16 + (lid & 15);
    const unsigned bk8 = ((unsigned)(lid >> 4)) * 16u;

    auto stageA = [&](int tap, int ci0, int s) {
        unsigned dH = sb + OFF_A0 + (unsigned)s * A_BUF;
        unsigned dL = dH + A_LO;
        #pragma unroll
        for (int i = tid; i < 1024; i += 512) {
            int cq = i & 7, row = i >> 3;
            size_t src = ((size_t)tap * 256 + co0 + row) * 256 + ci0 + cq * 8;
            unsigned swo = sw128((unsigned)(row * 128 + cq * 16));
            cp16(dH + swo, g_wa_hi + src);
            cp16(dL + swo, g_wa_lo + src);
        }
        cp_commit();
    };

    for (int cc = 0; cc < 4; cc++) {
        const int ci0 = cc << 6;
        __syncthreads();
        // ---- stage X patch via cp.async (zero-fill for halo) ----
        for (int i = tid; i < 6 * 66 * 8; i += 512) {
            int cq  = i & 7;
            int row = i >> 3;
            int hl  = row / 66;
            int wv  = row - hl * 66;
            int h = h0 + hl - 1;
            int w = wv - 1;
            bool ok = ((unsigned)h < 64u) && ((unsigned)w < 64u);
            size_t src = ok ? (((size_t)(h * 64 + w)) * 256 + ci0 + cq * 8) : 0;
            unsigned swo = sw128((unsigned)((hl * 68 + wv) * 128 + cq * 16));
            cp16z(sb + OFF_XH + swo, xh + src, ok);
            cp16z(sb + OFF_XL + swo, xl + src, ok);
        }
        stageA(0, ci0, 0);
        cp_wait0();
        __syncthreads();

        for (int tap = 0; tap < 9; tap++) {
            const int s  = tap & 1;
            const int dh = tap / 3 - 1;
            const int dw = tap % 3 - 1;
            if (tap < 8) stageA(tap + 1, ci0, s ^ 1);

            const unsigned AH = sb + OFF_A0 + (unsigned)s * A_BUF;
            const unsigned AL = AH + A_LO;

            unsigned b_rowoff[4];
            #pragma unroll
            for (int j = 0; j < 4; j++) {
                int hl = bn[j] >> 6, w = bn[j] & 63;
                b_rowoff[j] = (unsigned)(((hl + dh + 1) * 68 + (w + dw + 1)) * 128) + bk8;
            }

            #pragma unroll
            for (int ks = 0; ks < 4; ks++) {
                unsigned afH[2][4], bfH[4][4];
                #pragma unroll
                for (int mt = 0; mt < 2; mt++)
                    ldm_x4(afH[mt], AH + sw128(a_rowoff[mt] + ks * 32u));
                #pragma unroll
                for (int j = 0; j < 4; j++)
                    ldm_x4(bfH[j], sb + OFF_XH + sw128(b_rowoff[j] + ks * 32u));
                // term HH
                #pragma unroll
                for (int mt = 0; mt < 2; mt++)
                    #pragma unroll
                    for (int nt = 0; nt < 8; nt++)
                        mma16816(acc[mt][nt], afH[mt],
                                 bfH[nt >> 1][nt & 1], bfH[nt >> 1][(nt & 1) + 2]);
                // term LH (load afL, reuse bfH; afL dead after)
                {
                    unsigned afL[2][4];
                    #pragma unroll
                    for (int mt = 0; mt < 2; mt++)
                        ldm_x4(afL[mt], AL + sw128(a_rowoff[mt] + ks * 32u));
                    #pragma unroll
                    for (int mt = 0; mt < 2; mt++)
                        #pragma unroll
                        for (int nt = 0; nt < 8; nt++)
                            mma16816(acc[mt][nt], afL[mt],
                                     bfH[nt >> 1][nt & 1], bfH[nt >> 1][(nt & 1) + 2]);
                }
                // term HL (load bfL into bfH's registers; reuse afH)
                #pragma unroll
                for (int j = 0; j < 4; j++)
                    ldm_x4(bfH[j], sb + OFF_XL + sw128(b_rowoff[j] + ks * 32u));
                #pragma unroll
                for (int mt = 0; mt < 2; mt++)
                    #pragma unroll
                    for (int nt = 0; nt < 8; nt++)
                        mma16816(acc[mt][nt], afH[mt],
                                 bfH[nt >> 1][nt & 1], bfH[nt >> 1][(nt & 1) + 2]);
            }
            if (tap < 8) {
                cp_wait0();
                __syncthreads();
            }
        }
    }

    // ---- epilogue: store y as bf16 hi/lo pairs ----
    const int r4 = lid >> 2, c2 = (lid & 3) << 1;
    #pragma unroll
    for (int mt = 0; mt < 2; mt++) {
        #pragma unroll
        for (int nt = 0; nt < 8; nt++) {
            int co  = co0 + wm * 32 + mt * 16 + r4;
            int pix = n0 + wn * 64 + nt * 8 + c2;
            size_t base = ((size_t)(b * 256 + co)) * NPIX + pix;
            unsigned uh, ul;
            split2(acc[mt][nt][0], acc[mt][nt][1], uh, ul);
            *(unsigned*)(g_yh + base) = uh;
            *(unsigned*)(g_yl + base) = ul;
            split2(acc[mt][nt][2], acc[mt][nt][3], uh, ul);
            *(unsigned*)(g_yh + base + (size_t)8 * NPIX) = uh;
            *(unsigned*)(g_yl + base + (size_t)8 * NPIX) = ul;
        }
    }
}

// ---------------- kernel 5: ARMA solve, 2 slices (same channel) per CTA ----------------
#define PA_BYH 0u
#define PA_BYL 32768u
#define PA_GYH 65536u
#define PA_GYL 73728u
#define PA_GXH 81920u
#define PA_GXL 90112u
#define ARMA_SMEM 98304

__global__ __launch_bounds__(128, 2)
void arma_mma_kernel(float* __restrict__ out) {
    extern __shared__ char smem[];
    const unsigned sb = smem_u32(smem);
    const int tid = threadIdx.x;
    const int lid = tid & 31;
    const int wid = tid >> 5;
    const int c   = blockIdx.x & 255;
    const int bg  = blockIdx.x >> 8;
    const int slice0 = (2 * bg) * 256 + c;

    for (int i = tid; i < 2048; i += 128) {
        int r = i >> 3, cq = i & 7;
        int s = r >> 6, h = r & 63;
        size_t e = ((size_t)(slice0 + s * 256)) * 4096 + h * 64 + cq * 8;
        unsigned swo = sw128((unsigned)(r * 128 + cq * 16));
        cp16(sb + PA_BYH + swo, g_yh + e);
        cp16(sb + PA_BYL + swo, g_yl + e);
    }
    for (int i = tid; i < 512; i += 128) {
        int r = i >> 3, cq = i & 7;
        size_t e = (size_t)c * 4096 + r * 64 + cq * 8;
        unsigned swo = sw128((unsigned)(r * 128 + cq * 16));
        cp16(sb + PA_GYH + swo, g_gyT_hi + e);
        cp16(sb + PA_GYL + swo, g_gyT_lo + e);
        cp16(sb + PA_GXH + swo, g_gx_hi  + e);
        cp16(sb + PA_GXL + swo, g_gx_lo  + e);
    }
    cp_commit(); cp_wait0();
    __syncthreads();

    const int wm = wid & 1, wn = wid >> 1;
    unsigned a_rowoff[2];
    #pragma unroll
    for (int mt = 0; mt < 2; mt++) {
        int row = wm * 32 + mt * 16 + (lid & 7) + ((lid >> 3) & 1) * 8;
        a_rowoff[mt] = (unsigned)(row * 128) + ((unsigned)(lid >> 4)) * 16u;
    }
    unsigned b_off[4];
    #pragma unroll
    for (int j = 0; j < 4; j++)
        b_off[j] = (unsigned)((wn * 64 + j * 16 + (lid & 15)) * 128)
                 + ((unsigned)(lid >> 4)) * 16u;
    const int r4 = lid >> 2, cp2 = (lid & 3) << 1;

    float acc[2][8][4];
    #pragma unroll
    for (int mt = 0; mt < 2; mt++)
        #pragma unroll
        for (int nt = 0; nt < 8; nt++)
            #pragma unroll
            for (int k = 0; k < 4; k++) acc[mt][nt][k] = 0.f;

    #pragma unroll
    for (int ks = 0; ks < 4; ks++) {
        unsigned AH[2][4], AL[2][4], BH[4][4], BL[4][4];
        #pragma unroll
        for (int mt = 0; mt < 2; mt++) {
            ldm_x4(AH[mt], sb + PA_GYH + sw128(a_rowoff[mt] + ks * 32u));
            ldm_x4(AL[mt], sb + PA_GYL + sw128(a_rowoff[mt] + ks * 32u));
        }
        #pragma unroll
        for (int j = 0; j < 4; j++) {
            ldm_x4(BH[j], sb + PA_BYH + sw128(b_off[j] + ks * 32u));
            ldm_x4(BL[j], sb + PA_BYL + sw128(b_off[j] + ks * 32u));
        }
        #pragma unroll
        for (int mt = 0; mt < 2; mt++)
            #pragma unroll
            for (int nt = 0; nt < 8; nt++) {
                unsigned h0b = BH[nt >> 1][nt & 1], h1b = BH[nt >> 1][(nt & 1) + 2];
                mma16816(acc[mt][nt], AH[mt], h0b, h1b);
                mma16816(acc[mt][nt], AH[mt],
                         BL[nt >> 1][nt & 1], BL[nt >> 1][(nt & 1) + 2]);
                mma16816(acc[mt][nt], AL[mt], h0b, h1b);
            }
    }
    __syncthreads();

    #pragma unroll
    for (int mt = 0; mt < 2; mt++) {
        #pragma unroll
        for (int nt = 0; nt < 8; nt++) {
            int m = wm * 32 + mt * 16 + r4;
            int n = wn * 64 + nt * 8 + cp2;
            int row = (n & ~63) + m;
            int col = n & 63;
            unsigned uh, ul;
            split2(acc[mt][nt][0], acc[mt][nt][1], uh, ul);
            unsigned ad = sw128((unsigned)(row * 128 + col * 2));
            *(unsigned*)(smem + PA_BYH + ad) = uh;
            *(unsigned*)(smem + PA_BYL + ad) = ul;
            split2(acc[mt][nt][2], acc[mt][nt][3], uh, ul);
            ad = sw128((unsigned)((row + 8) * 128 + col * 2));
            *(unsigned*)(smem + PA_BYH + ad) = uh;
            *(unsigned*)(smem + PA_BYL + ad) = ul;
        }
    }
    __syncthreads();

    float o[2][8][4];
    #pragma unroll
    for (int mt = 0; mt < 2; mt++)
        #pragma unroll
        for (int nt = 0; nt < 8; nt++)
            #pragma unroll
            for (int k = 0; k < 4; k++) o[mt][nt][k] = 0.f;

    #pragma unroll
    for (int ks = 0; ks < 4; ks++) {
        unsigned AH[2][4], AL[2][4], BH[4][4], BL[4][4];
        #pragma unroll
        for (int mt = 0; mt < 2; mt++) {
            ldm_x4(AH[mt], sb + PA_GXH + sw128(a_rowoff[mt] + ks * 32u));
            ldm_x4(AL[mt], sb + PA_GXL + sw128(a_rowoff[mt] + ks * 32u));
        }
        #pragma unroll
        for (int j = 0; j < 4; j++) {
            ldm_x4(BH[j], sb + PA_BYH + sw128(b_off[j] + ks * 32u));
            ldm_x4(BL[j], sb + PA_BYL + sw128(b_off[j] + ks * 32u));
        }
        #pragma unroll
        for (int mt = 0; mt < 2; mt++)
            #pragma unroll
            for (int nt = 0; nt < 8; nt++) {
                unsigned h0b = BH[nt >> 1][nt & 1], h1b = BH[nt >> 1][(nt & 1) + 2];
                mma16816(o[mt][nt], AH[mt], h0b, h1b);
                mma16816(o[mt][nt], AH[mt],
                         BL[nt >> 1][nt & 1], BL[nt >> 1][(nt & 1) + 2]);
                mma16816(o[mt][nt], AL[mt], h0b, h1b);
            }
    }

    #pragma unroll
    for (int mt = 0; mt < 2; mt++) {
        #pragma unroll
        for (int nt = 0; nt < 8; nt++) {
            int m = wm * 32 + mt * 16 + r4;
            int n = wn * 64 + nt * 8 + cp2;
            int s = n >> 6;
            int j = n & 63;
            float* O = out + ((size_t)(slice0 + s * 256)) * 4096;
            *(float2*)(O + m * 64 + j)       = make_float2(o[mt][nt][0], o[mt][nt][1]);
            *(float2*)(O + (m + 8) * 64 + j) = make_float2(o[mt][nt][2], o[mt][nt][3]);
        }
    }
}

// ---------------- launcher ----------------
extern "C" void kernel_launch(void* const* d_in, const int* in_sizes, int n_in,
                              void* d_out, int out_size) {
    const float* x     = (const float*)d_in[0];
    const float* w     = (const float*)d_in[1];
    const float* alpha = (const float*)d_in[2];
    float* out = (float*)d_out;

    cudaFuncSetAttribute(conv_mma_kernel,
                         cudaFuncAttributeMaxDynamicSharedMemorySize, CONV_SMEM);
    cudaFuncSetAttribute(arma_mma_kernel,
                         cudaFuncAttributeMaxDynamicSharedMemorySize, ARMA_SMEM);

    wa_kernel<<<CCH, 256>>>(w);
    ginv_kernel<<<CCH, 128>>>(alpha);
    gmat_kernel<<<CCH, 256>>>();
    xt_kernel<<<dim3(64, 4, 32), 256>>>(x);
    conv_mma_kernel<<<dim3(16, 2, 32), 512, CONV_SMEM>>>();
    arma_mma_kernel<<<16 * 256, 128, ARMA_SMEM>>>(out);
}

// round 9
// speedup vs baseline: 1.2945x; 1.2786x over previous
#include <cuda_runtime.h>
#include <cuda_bf16.h>
#include <cuda_fp16.h>
#include <math.h>

// ---------------- problem constants ----------------
#define BSZ   32
#define CCH   256
#define NPIX  4096      // 64x64

// ---------------- scratch (device globals; no allocation) ----------------
__device__ __align__(16) __nv_bfloat16  g_yh[(size_t)BSZ * CCH * NPIX];   // conv out hi (bf16)
__device__ __align__(16) __nv_bfloat16  g_yl[(size_t)BSZ * CCH * NPIX];   // conv out lo (bf16)
__device__ __align__(16) __half         g_xt[(size_t)BSZ * NPIX * CCH];   // x transposed fp16
__device__ __align__(16) __half         g_wa_h[9 * CCH * CCH];            // weights fp16 hi
__device__ __align__(16) __half         g_wa_l[9 * CCH * CCH];            // weights fp16 lo
__device__ float                        g_ginv[2 * CCH * 64];
__device__ __align__(16) __nv_bfloat16  g_gyT_hi[CCH * 4096];
__device__ __align__(16) __nv_bfloat16  g_gyT_lo[CCH * 4096];
__device__ __align__(16) __nv_bfloat16  g_gx_hi[CCH * 4096];
__device__ __align__(16) __nv_bfloat16  g_gx_lo[CCH * 4096];

// ---------------- helpers ----------------
__device__ __forceinline__ unsigned smem_u32(const void* p) {
    unsigned r;
    asm("{ .reg .u64 t; cvta.to.shared.u64 t, %1; cvt.u32.u64 %0, t; }" : "=r"(r) : "l"(p));
    return r;
}
__device__ __forceinline__ unsigned sw128(unsigned off) { return off ^ ((off >> 3) & 0x70); }

__device__ __forceinline__ void ldm_x4(unsigned* r, unsigned addr) {
    asm volatile("ldmatrix.sync.aligned.m8n8.x4.shared.b16 {%0,%1,%2,%3}, [%4];"
        : "=r"(r[0]), "=r"(r[1]), "=r"(r[2]), "=r"(r[3]) : "r"(addr));
}
__device__ __forceinline__ void mma_bf16(float* d, const unsigned* a,
                                         unsigned b0, unsigned b1) {
    asm volatile("mma.sync.aligned.m16n8k16.row.col.f32.bf16.bf16.f32 "
        "{%0,%1,%2,%3}, {%4,%5,%6,%7}, {%8,%9}, {%0,%1,%2,%3};"
        : "+f"(d[0]), "+f"(d[1]), "+f"(d[2]), "+f"(d[3])
        : "r"(a[0]), "r"(a[1]), "r"(a[2]), "r"(a[3]), "r"(b0), "r"(b1));
}
__device__ __forceinline__ void mma_f16(float* d, const unsigned* a,
                                        unsigned b0, unsigned b1) {
    asm volatile("mma.sync.aligned.m16n8k16.row.col.f32.f16.f16.f32 "
        "{%0,%1,%2,%3}, {%4,%5,%6,%7}, {%8,%9}, {%0,%1,%2,%3};"
        : "+f"(d[0]), "+f"(d[1]), "+f"(d[2]), "+f"(d[3])
        : "r"(a[0]), "r"(a[1]), "r"(a[2]), "r"(a[3]), "r"(b0), "r"(b1));
}
__device__ __forceinline__ void cp16(unsigned dst, const void* src) {
    asm volatile("cp.async.cg.shared.global [%0], [%1], 16;" :: "r"(dst), "l"(src));
}
__device__ __forceinline__ void cp16z(unsigned dst, const void* src, bool ok) {
    int sz = ok ? 16 : 0;
    asm volatile("cp.async.cg.shared.global [%0], [%1], 16, %2;"
                 :: "r"(dst), "l"(src), "r"(sz));
}
__device__ __forceinline__ void cp_commit() {
    asm volatile("cp.async.commit_group;" ::: "memory");
}
__device__ __forceinline__ void cp_wait0() {
    asm volatile("cp.async.wait_group 0;" ::: "memory");
}
// split a float pair into packed bf16x2 hi + lo words
__device__ __forceinline__ void split2(float a, float b, unsigned& uh, unsigned& ul) {
    __nv_bfloat16 ha = __float2bfloat16(a), hb = __float2bfloat16(b);
    float ra = a - __bfloat162float(ha), rb = b - __bfloat162float(hb);
    __nv_bfloat16 la = __float2bfloat16(ra), lb = __float2bfloat16(rb);
    uh = (unsigned)__bfloat16_as_ushort(ha) | ((unsigned)__bfloat16_as_ushort(hb) << 16);
    ul = (unsigned)__bfloat16_as_ushort(la) | ((unsigned)__bfloat16_as_ushort(lb) << 16);
}
// split a float pair into packed fp16x2 hi + lo words
__device__ __forceinline__ void split2h(float a, float b, unsigned& uh, unsigned& ul) {
    __half ha = __float2half_rn(a), hb = __float2half_rn(b);
    float ra = a - __half2float(ha), rb = b - __half2float(hb);
    __half la = __float2half_rn(ra), lb = __float2half_rn(rb);
    uh = (unsigned)__half_as_ushort(ha) | ((unsigned)__half_as_ushort(hb) << 16);
    ul = (unsigned)__half_as_ushort(la) | ((unsigned)__half_as_ushort(lb) << 16);
}

// ---------------- kernel 1: weights -> [tap][co][ci] fp16 hi/lo ----------------
__global__ void wa_kernel(const float* __restrict__ w) {
    __shared__ float s[2304];
    const int co  = blockIdx.x;
    const int tid = threadIdx.x;
    for (int i = tid; i < 2304; i += 256) s[i] = w[(size_t)co * 2304 + i];
    __syncthreads();
    for (int it = tid; it < 288; it += 256) {   // 9 taps x 32 ci-groups
        int tap = it >> 5, grp = it & 31;
        unsigned h4[4], l4[4];
        #pragma unroll
        for (int k = 0; k < 4; k++) {
            float a = s[(grp * 8 + k * 2) * 9 + tap];
            float b = s[(grp * 8 + k * 2 + 1) * 9 + tap];
            split2h(a, b, h4[k], l4[k]);
        }
        size_t o = ((size_t)tap * 256 + co) * 256 + grp * 8;
        *(uint4*)(g_wa_h + o) = make_uint4(h4[0], h4[1], h4[2], h4[3]);
        *(uint4*)(g_wa_l + o) = make_uint4(l4[0], l4[1], l4[2], l4[3]);
    }
}

// ---------------- kernel 2: x -> transposed fp16 (single) ----------------
__global__ void xt_kernel(const float* __restrict__ x) {
    __shared__ float s[64][65];
    int p0  = blockIdx.x * 64;
    int ci0 = blockIdx.y * 64;
    int b   = blockIdx.z;
    int tid = threadIdx.x;
    for (int i = tid; i < 4096; i += 256) {
        int ci = i >> 6, p = i & 63;
        s[ci][p] = x[((size_t)(b * 256 + ci0 + ci)) * NPIX + p0 + p];
    }
    __syncthreads();
    for (int i = tid; i < 512; i += 256) {      // 64 pix x 8 ci-groups
        int pix = i >> 3, grp = i & 7;
        unsigned h4[4];
        #pragma unroll
        for (int k = 0; k < 4; k++) {
            __half a = __float2half_rn(s[grp * 8 + k * 2][pix]);
            __half b = __float2half_rn(s[grp * 8 + k * 2 + 1][pix]);
            h4[k] = (unsigned)__half_as_ushort(a) | ((unsigned)__half_as_ushort(b) << 16);
        }
        size_t o = ((size_t)b * NPIX + p0 + pix) * 256 + ci0 + grp * 8;
        *(uint4*)(g_xt + o) = make_uint4(h4[0], h4[1], h4[2], h4[3]);
    }
}

// ---------------- kernel 3: circulant inverse kernels ----------------
__global__ void ginv_kernel(const float* __restrict__ alpha) {
    int c = blockIdx.x;
    int t = threadIdx.x;
    int dir = t >> 6;
    int n   = t & 63;
    float t00 = tanhf(alpha[c*4+0]), t01 = tanhf(alpha[c*4+1]);
    float t10 = tanhf(alpha[c*4+2]), t11 = tanhf(alpha[c*4+3]);
    const float R = 0.70710678118654752440f;
    float a0, a2;
    if (dir == 0) { a0 = (t00 + t01) * R; a2 = (t01 - t00) * R; }
    else          { a0 = (t10 + t11) * R; a2 = (t11 - t10) * R; }
    double ar = (double)a0 + (double)a2;
    double ai = (double)a0 - (double)a2;
    double s = 0.0;
    for (int u = 0; u < 64; u++) {
        double th  = (2.0 * 3.14159265358979323846 / 64.0) * (double)u;
        double Fre = 1.0 + ar * cos(th);
        double Fim = ai * sin(th);
        double den = Fre * Fre + Fim * Fim;
        double ang = th * (double)n;
        s += (cos(ang) * Fre + sin(ang) * Fim) / den;
    }
    g_ginv[(dir * CCH + c) * 64 + n] = (float)(s / 64.0);
}

// ---------------- kernel 3b: circulant matrices (bf16 hi/lo) ----------------
__global__ void gmat_kernel() {
    int c   = blockIdx.x;
    int tid = threadIdx.x;
    __shared__ float gx[64], gy[64];
    if (tid < 64)                 gx[tid]      = g_ginv[c * 64 + tid];
    else if (tid < 128)           gy[tid - 64] = g_ginv[(CCH + c) * 64 + (tid - 64)];
    __syncthreads();
    for (int i = tid; i < 512; i += 256) {
        int r = i >> 3, grp = i & 7;
        unsigned xh4[4], xl4[4], yh4[4], yl4[4];
        #pragma unroll
        for (int k = 0; k < 4; k++) {
            int q0 = grp * 8 + k * 2;
            split2(gx[(r - q0) & 63], gx[(r - q0 - 1) & 63], xh4[k], xl4[k]);
            split2(gy[(r - q0) & 63], gy[(r - q0 - 1) & 63], yh4[k], yl4[k]);
        }
        size_t o = (size_t)c * 4096 + r * 64 + grp * 8;
        *(uint4*)(g_gx_hi  + o) = make_uint4(xh4[0], xh4[1], xh4[2], xh4[3]);
        *(uint4*)(g_gx_lo  + o) = make_uint4(xl4[0], xl4[1], xl4[2], xl4[3]);
        *(uint4*)(g_gyT_hi + o) = make_uint4(yh4[0], yh4[1], yh4[2], yh4[3]);
        *(uint4*)(g_gyT_lo + o) = make_uint4(yl4[0], yl4[1], yl4[2], yl4[3]);
    }
}

// ---------------- kernel 4: implicit-GEMM conv, fp16 2-term ----------------
// CTA: M=128 co x N=128 pixels (2 image rows). 256 threads = 8 warps (4M x 2N),
// warp tile 32x64. Terms: Wh*X + Wl*X. A double-buffered, 2 CTAs/SM.
#define XP_ROWS  (4 * 68)
#define XP_BYTES (XP_ROWS * 128)       // 34816
#define OFF_X  0u
#define OFF_A0 34816u
#define A_BUF  32768u
#define A_LO   16384u
#define CONV_SMEM (OFF_A0 + 2 * A_BUF) // 100352

__global__ __launch_bounds__(256, 2)
void conv_mma_kernel() {
    extern __shared__ char smem[];
    const unsigned sb = smem_u32(smem);
    const int tid = threadIdx.x;
    const int lid = tid & 31;
    const int wid = tid >> 5;
    const int wm  = wid & 3;            // 0..3 (32 co each)
    const int wn  = wid >> 2;           // 0..1 (64 pixels each)

    const int n0  = blockIdx.x * 128;   // pixel base (2 image rows)
    const int h0  = n0 >> 6;
    const int co0 = blockIdx.y * 128;
    const int b   = blockIdx.z;

    const __half* xp = g_xt + (size_t)b * NPIX * 256;

    float acc[2][8][4];
    #pragma unroll
    for (int mt = 0; mt < 2; mt++)
        #pragma unroll
        for (int nt = 0; nt < 8; nt++)
            #pragma unroll
            for (int k = 0; k < 4; k++) acc[mt][nt][k] = 0.f;

    unsigned a_rowoff[2];
    #pragma unroll
    for (int mt = 0; mt < 2; mt++) {
        int row = wm * 32 + mt * 16 + (lid & 7) + ((lid >> 3) & 1) * 8;
        a_rowoff[mt] = (unsigned)(row * 128) + ((unsigned)(lid >> 4)) * 16u;
    }
    int bn[4];
    #pragma unroll
    for (int j = 0; j < 4; j++) bn[j] = wn * 64 + j * 16 + (lid & 15);
    const unsigned bk8 = ((unsigned)(lid >> 4)) * 16u;

    auto stageA = [&](int tap, int ci0, int s) {
        unsigned dH = sb + OFF_A0 + (unsigned)s * A_BUF;
        unsigned dL = dH + A_LO;
        #pragma unroll
        for (int i = tid; i < 1024; i += 256) {
            int cq = i & 7, row = i >> 3;
            size_t src = ((size_t)tap * 256 + co0 + row) * 256 + ci0 + cq * 8;
            unsigned swo = sw128((unsigned)(row * 128 + cq * 16));
            cp16(dH + swo, g_wa_h + src);
            cp16(dL + swo, g_wa_l + src);
        }
        cp_commit();
    };

    for (int cc = 0; cc < 4; cc++) {
        const int ci0 = cc << 6;
        __syncthreads();
        // ---- stage X patch (rows h0-1..h0+2, cols -1..64), fp16 single ----
        for (int i = tid; i < 4 * 66 * 8; i += 256) {
            int cq  = i & 7;
            int row = i >> 3;
            int hl  = row / 66;
            int wv  = row - hl * 66;
            int h = h0 + hl - 1;
            int w = wv - 1;
            bool ok = ((unsigned)h < 64u) && ((unsigned)w < 64u);
            size_t src = ok ? (((size_t)(h * 64 + w)) * 256 + ci0 + cq * 8) : 0;
            unsigned swo = sw128((unsigned)((hl * 68 + wv) * 128 + cq * 16));
            cp16z(sb + OFF_X + swo, xp + src, ok);
        }
        stageA(0, ci0, 0);
        cp_wait0();
        __syncthreads();

        for (int tap = 0; tap < 9; tap++) {
            const int s  = tap & 1;
            const int dh = tap / 3 - 1;
            const int dw = tap % 3 - 1;
            if (tap < 8) stageA(tap + 1, ci0, s ^ 1);

            const unsigned AH = sb + OFF_A0 + (unsigned)s * A_BUF;
            const unsigned AL = AH + A_LO;

            unsigned b_rowoff[4];
            #pragma unroll
            for (int j = 0; j < 4; j++) {
                int hl = bn[j] >> 6, w = bn[j] & 63;
                b_rowoff[j] = (unsigned)(((hl + dh + 1) * 68 + (w + dw + 1)) * 128) + bk8;
            }

            #pragma unroll
            for (int ks = 0; ks < 4; ks++) {
                unsigned af[2][4], bf[4][4];
                #pragma unroll
                for (int mt = 0; mt < 2; mt++)
                    ldm_x4(af[mt], AH + sw128(a_rowoff[mt] + ks * 32u));
                #pragma unroll
                for (int j = 0; j < 4; j++)
                    ldm_x4(bf[j], sb + OFF_X + sw128(b_rowoff[j] + ks * 32u));
                // term Wh*X
                #pragma unroll
                for (int mt = 0; mt < 2; mt++)
                    #pragma unroll
                    for (int nt = 0; nt < 8; nt++)
                        mma_f16(acc[mt][nt], af[mt],
                                bf[nt >> 1][nt & 1], bf[nt >> 1][(nt & 1) + 2]);
                // term Wl*X (reload A regs, reuse bf)
                #pragma unroll
                for (int mt = 0; mt < 2; mt++)
                    ldm_x4(af[mt], AL + sw128(a_rowoff[mt] + ks * 32u));
                #pragma unroll
                for (int mt = 0; mt < 2; mt++)
                    #pragma unroll
                    for (int nt = 0; nt < 8; nt++)
                        mma_f16(acc[mt][nt], af[mt],
                                bf[nt >> 1][nt & 1], bf[nt >> 1][(nt & 1) + 2]);
            }
            if (tap < 8) {
                cp_wait0();
                __syncthreads();
            }
        }
    }

    // ---- epilogue: store y as bf16 hi/lo pairs (arma input) ----
    const int r4 = lid >> 2, c2 = (lid & 3) << 1;
    #pragma unroll
    for (int mt = 0; mt < 2; mt++) {
        #pragma unroll
        for (int nt = 0; nt < 8; nt++) {
            int co  = co0 + wm * 32 + mt * 16 + r4;
            int pix = n0 + wn * 64 + nt * 8 + c2;
            size_t base = ((size_t)(b * 256 + co)) * NPIX + pix;
            unsigned uh, ul;
            split2(acc[mt][nt][0], acc[mt][nt][1], uh, ul);
            *(unsigned*)(g_yh + base) = uh;
            *(unsigned*)(g_yl + base) = ul;
            split2(acc[mt][nt][2], acc[mt][nt][3], uh, ul);
            *(unsigned*)(g_yh + base + (size_t)8 * NPIX) = uh;
            *(unsigned*)(g_yl + base + (size_t)8 * NPIX) = ul;
        }
    }
}

// ---------------- kernel 5: ARMA solve, 2 slices (same channel) per CTA ----------------
#define PA_BYH 0u
#define PA_BYL 32768u
#define PA_GYH 65536u
#define PA_GYL 73728u
#define PA_GXH 81920u
#define PA_GXL 90112u
#define ARMA_SMEM 98304

__global__ __launch_bounds__(128, 2)
void arma_mma_kernel(float* __restrict__ out) {
    extern __shared__ char smem[];
    const unsigned sb = smem_u32(smem);
    const int tid = threadIdx.x;
    const int lid = tid & 31;
    const int wid = tid >> 5;
    const int c   = blockIdx.x & 255;
    const int bg  = blockIdx.x >> 8;
    const int slice0 = (2 * bg) * 256 + c;

    for (int i = tid; i < 2048; i += 128) {
        int r = i >> 3, cq = i & 7;
        int s = r >> 6, h = r & 63;
        size_t e = ((size_t)(slice0 + s * 256)) * 4096 + h * 64 + cq * 8;
        unsigned swo = sw128((unsigned)(r * 128 + cq * 16));
        cp16(sb + PA_BYH + swo, g_yh + e);
        cp16(sb + PA_BYL + swo, g_yl + e);
    }
    for (int i = tid; i < 512; i += 128) {
        int r = i >> 3, cq = i & 7;
        size_t e = (size_t)c * 4096 + r * 64 + cq * 8;
        unsigned swo = sw128((unsigned)(r * 128 + cq * 16));
        cp16(sb + PA_GYH + swo, g_gyT_hi + e);
        cp16(sb + PA_GYL + swo, g_gyT_lo + e);
        cp16(sb + PA_GXH + swo, g_gx_hi  + e);
        cp16(sb + PA_GXL + swo, g_gx_lo  + e);
    }
    cp_commit(); cp_wait0();
    __syncthreads();

    const int wm = wid & 1, wn = wid >> 1;
    unsigned a_rowoff[2];
    #pragma unroll
    for (int mt = 0; mt < 2; mt++) {
        int row = wm * 32 + mt * 16 + (lid & 7) + ((lid >> 3) & 1) * 8;
        a_rowoff[mt] = (unsigned)(row * 128) + ((unsigned)(lid >> 4)) * 16u;
    }
    unsigned b_off[4];
    #pragma unroll
    for (int j = 0; j < 4; j++)
        b_off[j] = (unsigned)((wn * 64 + j * 16 + (lid & 15)) * 128)
                 + ((unsigned)(lid >> 4)) * 16u;
    const int r4 = lid >> 2, cp2 = (lid & 3) << 1;

    float acc[2][8][4];
    #pragma unroll
    for (int mt = 0; mt < 2; mt++)
        #pragma unroll
        for (int nt = 0; nt < 8; nt++)
            #pragma unroll
            for (int k = 0; k < 4; k++) acc[mt][nt][k] = 0.f;

    #pragma unroll
    for (int ks = 0; ks < 4; ks++) {
        unsigned AH[2][4], AL[2][4], BH[4][4], BL[4][4];
        #pragma unroll
        for (int mt = 0; mt < 2; mt++) {
            ldm_x4(AH[mt], sb + PA_GYH + sw128(a_rowoff[mt] + ks * 32u));
            ldm_x4(AL[mt], sb + PA_GYL + sw128(a_rowoff[mt] + ks * 32u));
        }
        #pragma unroll
        for (int j = 0; j < 4; j++) {
            ldm_x4(BH[j], sb + PA_BYH + sw128(b_off[j] + ks * 32u));
            ldm_x4(BL[j], sb + PA_BYL + sw128(b_off[j] + ks * 32u));
        }
        #pragma unroll
        for (int mt = 0; mt < 2; mt++)
            #pragma unroll
            for (int nt = 0; nt < 8; nt++) {
                unsigned h0b = BH[nt >> 1][nt & 1], h1b = BH[nt >> 1][(nt & 1) + 2];
                mma_bf16(acc[mt][nt], AH[mt], h0b, h1b);
                mma_bf16(acc[mt][nt], AH[mt],
                         BL[nt >> 1][nt & 1], BL[nt >> 1][(nt & 1) + 2]);
                mma_bf16(acc[mt][nt], AL[mt], h0b, h1b);
            }
    }
    __syncthreads();

    #pragma unroll
    for (int mt = 0; mt < 2; mt++) {
        #pragma unroll
        for (int nt = 0; nt < 8; nt++) {
            int m = wm * 32 + mt * 16 + r4;
            int n = wn * 64 + nt * 8 + cp2;
            int row = (n & ~63) + m;
            int col = n & 63;
            unsigned uh, ul;
            split2(acc[mt][nt][0], acc[mt][nt][1], uh, ul);
            unsigned ad = sw128((unsigned)(row * 128 + col * 2));
            *(unsigned*)(smem + PA_BYH + ad) = uh;
            *(unsigned*)(smem + PA_BYL + ad) = ul;
            split2(acc[mt][nt][2], acc[mt][nt][3], uh, ul);
            ad = sw128((unsigned)((row + 8) * 128 + col * 2));
            *(unsigned*)(smem + PA_BYH + ad) = uh;
            *(unsigned*)(smem + PA_BYL + ad) = ul;
        }
    }
    __syncthreads();

    float o[2][8][4];
    #pragma unroll
    for (int mt = 0; mt < 2; mt++)
        #pragma unroll
        for (int nt = 0; nt < 8; nt++)
            #pragma unroll
            for (int k = 0; k < 4; k++) o[mt][nt][k] = 0.f;

    #pragma unroll
    for (int ks = 0; ks < 4; ks++) {
        unsigned AH[2][4], AL[2][4], BH[4][4], BL[4][4];
        #pragma unroll
        for (int mt = 0; mt < 2; mt++) {
            ldm_x4(AH[mt], sb + PA_GXH + sw128(a_rowoff[mt] + ks * 32u));
            ldm_x4(AL[mt], sb + PA_GXL + sw128(a_rowoff[mt] + ks * 32u));
        }
        #pragma unroll
        for (int j = 0; j < 4; j++) {
            ldm_x4(BH[j], sb + PA_BYH + sw128(b_off[j] + ks * 32u));
            ldm_x4(BL[j], sb + PA_BYL + sw128(b_off[j] + ks * 32u));
        }
        #pragma unroll
        for (int mt = 0; mt < 2; mt++)
            #pragma unroll
            for (int nt = 0; nt < 8; nt++) {
                unsigned h0b = BH[nt >> 1][nt & 1], h1b = BH[nt >> 1][(nt & 1) + 2];
                mma_bf16(o[mt][nt], AH[mt], h0b, h1b);
                mma_bf16(o[mt][nt], AH[mt],
                         BL[nt >> 1][nt & 1], BL[nt >> 1][(nt & 1) + 2]);
                mma_bf16(o[mt][nt], AL[mt], h0b, h1b);
            }
    }

    #pragma unroll
    for (int mt = 0; mt < 2; mt++) {
        #pragma unroll
        for (int nt = 0; nt < 8; nt++) {
            int m = wm * 32 + mt * 16 + r4;
            int n = wn * 64 + nt * 8 + cp2;
            int s = n >> 6;
            int j = n & 63;
            float* O = out + ((size_t)(slice0 + s * 256)) * 4096;
            *(float2*)(O + m * 64 + j)       = make_float2(o[mt][nt][0], o[mt][nt][1]);
            *(float2*)(O + (m + 8) * 64 + j) = make_float2(o[mt][nt][2], o[mt][nt][3]);
        }
    }
}

// ---------------- launcher ----------------
extern "C" void kernel_launch(void* const* d_in, const int* in_sizes, int n_in,
                              void* d_out, int out_size) {
    const float* x     = (const float*)d_in[0];
    const float* w     = (const float*)d_in[1];
    const float* alpha = (const float*)d_in[2];
    float* out = (float*)d_out;

    cudaFuncSetAttribute(conv_mma_kernel,
                         cudaFuncAttributeMaxDynamicSharedMemorySize, CONV_SMEM);
    cudaFuncSetAttribute(arma_mma_kernel,
                         cudaFuncAttributeMaxDynamicSharedMemorySize, ARMA_SMEM);

    wa_kernel<<<CCH, 256>>>(w);
    ginv_kernel<<<CCH, 128>>>(alpha);
    gmat_kernel<<<CCH, 256>>>();
    xt_kernel<<<dim3(64, 4, 32), 256>>>(x);
    conv_mma_kernel<<<dim3(32, 2, 32), 256, CONV_SMEM>>>();
    arma_mma_kernel<<<16 * 256, 128, ARMA_SMEM>>>(out);
}

// round 10
// speedup vs baseline: 1.7493x; 1.3513x over previous
#include <cuda_runtime.h>
#include <cuda_bf16.h>
#include <cuda_fp16.h>
#include <math.h>

// ---------------- problem constants ----------------
#define BSZ   32
#define CCH   256
#define NPIX  4096      // 64x64

// ---------------- scratch (device globals; no allocation) ----------------
__device__ __align__(16) __nv_bfloat16  g_yh[(size_t)BSZ * CCH * NPIX];   // conv out hi (bf16)
__device__ __align__(16) __nv_bfloat16  g_yl[(size_t)BSZ * CCH * NPIX];   // conv out lo (bf16)
__device__ __align__(16) __half         g_xt[(size_t)BSZ * NPIX * CCH];   // x transposed fp16
__device__ __align__(16) __half         g_wa[9 * CCH * CCH];              // weights fp16
__device__ float                        g_ginv[2 * CCH * 64];
__device__ __align__(16) __nv_bfloat16  g_gyT_hi[CCH * 4096];
__device__ __align__(16) __nv_bfloat16  g_gyT_lo[CCH * 4096];
__device__ __align__(16) __nv_bfloat16  g_gx_hi[CCH * 4096];
__device__ __align__(16) __nv_bfloat16  g_gx_lo[CCH * 4096];

// ---------------- helpers ----------------
__device__ __forceinline__ unsigned smem_u32(const void* p) {
    unsigned r;
    asm("{ .reg .u64 t; cvta.to.shared.u64 t, %1; cvt.u32.u64 %0, t; }" : "=r"(r) : "l"(p));
    return r;
}
__device__ __forceinline__ unsigned sw128(unsigned off) { return off ^ ((off >> 3) & 0x70); }

__device__ __forceinline__ void ldm_x4(unsigned* r, unsigned addr) {
    asm volatile("ldmatrix.sync.aligned.m8n8.x4.shared.b16 {%0,%1,%2,%3}, [%4];"
        : "=r"(r[0]), "=r"(r[1]), "=r"(r[2]), "=r"(r[3]) : "r"(addr));
}
__device__ __forceinline__ void mma_bf16(float* d, const unsigned* a,
                                         unsigned b0, unsigned b1) {
    asm volatile("mma.sync.aligned.m16n8k16.row.col.f32.bf16.bf16.f32 "
        "{%0,%1,%2,%3}, {%4,%5,%6,%7}, {%8,%9}, {%0,%1,%2,%3};"
        : "+f"(d[0]), "+f"(d[1]), "+f"(d[2]), "+f"(d[3])
        : "r"(a[0]), "r"(a[1]), "r"(a[2]), "r"(a[3]), "r"(b0), "r"(b1));
}
__device__ __forceinline__ void mma_f16(float* d, const unsigned* a,
                                        unsigned b0, unsigned b1) {
    asm volatile("mma.sync.aligned.m16n8k16.row.col.f32.f16.f16.f32 "
        "{%0,%1,%2,%3}, {%4,%5,%6,%7}, {%8,%9}, {%0,%1,%2,%3};"
        : "+f"(d[0]), "+f"(d[1]), "+f"(d[2]), "+f"(d[3])
        : "r"(a[0]), "r"(a[1]), "r"(a[2]), "r"(a[3]), "r"(b0), "r"(b1));
}
__device__ __forceinline__ void cp16(unsigned dst, const void* src) {
    asm volatile("cp.async.cg.shared.global [%0], [%1], 16;" :: "r"(dst), "l"(src));
}
__device__ __forceinline__ void cp16z(unsigned dst, const void* src, bool ok) {
    int sz = ok ? 16 : 0;
    asm volatile("cp.async.cg.shared.global [%0], [%1], 16, %2;"
                 :: "r"(dst), "l"(src), "r"(sz));
}
__device__ __forceinline__ void cp_commit() {
    asm volatile("cp.async.commit_group;" ::: "memory");
}
__device__ __forceinline__ void cp_wait0() {
    asm volatile("cp.async.wait_group 0;" ::: "memory");
}
// split a float pair into packed bf16x2 hi + lo words
__device__ __forceinline__ void split2(float a, float b, unsigned& uh, unsigned& ul) {
    __nv_bfloat16 ha = __float2bfloat16(a), hb = __float2bfloat16(b);
    float ra = a - __bfloat162float(ha), rb = b - __bfloat162float(hb);
    __nv_bfloat16 la = __float2bfloat16(ra), lb = __float2bfloat16(rb);
    uh = (unsigned)__bfloat16_as_ushort(ha) | ((unsigned)__bfloat16_as_ushort(hb) << 16);
    ul = (unsigned)__bfloat16_as_ushort(la) | ((unsigned)__bfloat16_as_ushort(lb) << 16);
}

// ---------------- kernel 1: weights -> [tap][co][ci] fp16 ----------------
__global__ void wa_kernel(const float* __restrict__ w) {
    __shared__ float s[2304];
    const int co  = blockIdx.x;
    const int tid = threadIdx.x;
    for (int i = tid; i < 2304; i += 256) s[i] = w[(size_t)co * 2304 + i];
    __syncthreads();
    for (int it = tid; it < 288; it += 256) {   // 9 taps x 32 ci-groups
        int tap = it >> 5, grp = it & 31;
        unsigned h4[4];
        #pragma unroll
        for (int k = 0; k < 4; k++) {
            __half a = __float2half_rn(s[(grp * 8 + k * 2) * 9 + tap]);
            __half b = __float2half_rn(s[(grp * 8 + k * 2 + 1) * 9 + tap]);
            h4[k] = (unsigned)__half_as_ushort(a) | ((unsigned)__half_as_ushort(b) << 16);
        }
        size_t o = ((size_t)tap * 256 + co) * 256 + grp * 8;
        *(uint4*)(g_wa + o) = make_uint4(h4[0], h4[1], h4[2], h4[3]);
    }
}

// ---------------- kernel 2: x -> transposed fp16 ----------------
__global__ void xt_kernel(const float* __restrict__ x) {
    __shared__ float s[64][65];
    int p0  = blockIdx.x * 64;
    int ci0 = blockIdx.y * 64;
    int b   = blockIdx.z;
    int tid = threadIdx.x;
    for (int i = tid; i < 4096; i += 256) {
        int ci = i >> 6, p = i & 63;
        s[ci][p] = x[((size_t)(b * 256 + ci0 + ci)) * NPIX + p0 + p];
    }
    __syncthreads();
    for (int i = tid; i < 512; i += 256) {
        int pix = i >> 3, grp = i & 7;
        unsigned h4[4];
        #pragma unroll
        for (int k = 0; k < 4; k++) {
            __half a = __float2half_rn(s[grp * 8 + k * 2][pix]);
            __half b = __float2half_rn(s[grp * 8 + k * 2 + 1][pix]);
            h4[k] = (unsigned)__half_as_ushort(a) | ((unsigned)__half_as_ushort(b) << 16);
        }
        size_t o = ((size_t)b * NPIX + p0 + pix) * 256 + ci0 + grp * 8;
        *(uint4*)(g_xt + o) = make_uint4(h4[0], h4[1], h4[2], h4[3]);
    }
}

// ---------------- kernel 3: circulant inverse kernels ----------------
__global__ void ginv_kernel(const float* __restrict__ alpha) {
    int c = blockIdx.x;
    int t = threadIdx.x;
    int dir = t >> 6;
    int n   = t & 63;
    float t00 = tanhf(alpha[c*4+0]), t01 = tanhf(alpha[c*4+1]);
    float t10 = tanhf(alpha[c*4+2]), t11 = tanhf(alpha[c*4+3]);
    const float R = 0.70710678118654752440f;
    float a0, a2;
    if (dir == 0) { a0 = (t00 + t01) * R; a2 = (t01 - t00) * R; }
    else          { a0 = (t10 + t11) * R; a2 = (t11 - t10) * R; }
    double ar = (double)a0 + (double)a2;
    double ai = (double)a0 - (double)a2;
    double s = 0.0;
    for (int u = 0; u < 64; u++) {
        double th  = (2.0 * 3.14159265358979323846 / 64.0) * (double)u;
        double Fre = 1.0 + ar * cos(th);
        double Fim = ai * sin(th);
        double den = Fre * Fre + Fim * Fim;
        double ang = th * (double)n;
        s += (cos(ang) * Fre + sin(ang) * Fim) / den;
    }
    g_ginv[(dir * CCH + c) * 64 + n] = (float)(s / 64.0);
}

// ---------------- kernel 3b: circulant matrices (bf16 hi/lo) ----------------
__global__ void gmat_kernel() {
    int c   = blockIdx.x;
    int tid = threadIdx.x;
    __shared__ float gx[64], gy[64];
    if (tid < 64)                 gx[tid]      = g_ginv[c * 64 + tid];
    else if (tid < 128)           gy[tid - 64] = g_ginv[(CCH + c) * 64 + (tid - 64)];
    __syncthreads();
    for (int i = tid; i < 512; i += 256) {
        int r = i >> 3, grp = i & 7;
        unsigned xh4[4], xl4[4], yh4[4], yl4[4];
        #pragma unroll
        for (int k = 0; k < 4; k++) {
            int q0 = grp * 8 + k * 2;
            split2(gx[(r - q0) & 63], gx[(r - q0 - 1) & 63], xh4[k], xl4[k]);
            split2(gy[(r - q0) & 63], gy[(r - q0 - 1) & 63], yh4[k], yl4[k]);
        }
        size_t o = (size_t)c * 4096 + r * 64 + grp * 8;
        *(uint4*)(g_gx_hi  + o) = make_uint4(xh4[0], xh4[1], xh4[2], xh4[3]);
        *(uint4*)(g_gx_lo  + o) = make_uint4(xl4[0], xl4[1], xl4[2], xl4[3]);
        *(uint4*)(g_gyT_hi + o) = make_uint4(yh4[0], yh4[1], yh4[2], yh4[3]);
        *(uint4*)(g_gyT_lo + o) = make_uint4(yl4[0], yl4[1], yl4[2], yl4[3]);
    }
}

// ---------------- kernel 4: implicit-GEMM conv, single-term fp16 ----------------
// CTA: M=128 co x N=128 pixels. 256 threads = 8 warps (4M x 2N), warp tile 32x64.
// W fp16, X fp16, fp32 accum. A double-buffered, 2 CTAs/SM.
#define XP_ROWS  (4 * 68)
#define XP_BYTES (XP_ROWS * 128)       // 34816
#define OFF_X  0u
#define OFF_A0 34816u
#define A_BUF  16384u
#define CONV_SMEM (OFF_A0 + 2 * A_BUF) // 67584

__global__ __launch_bounds__(256, 2)
void conv_mma_kernel() {
    extern __shared__ char smem[];
    const unsigned sb = smem_u32(smem);
    const int tid = threadIdx.x;
    const int lid = tid & 31;
    const int wid = tid >> 5;
    const int wm  = wid & 3;            // 0..3 (32 co each)
    const int wn  = wid >> 2;           // 0..1 (64 pixels each)

    const int n0  = blockIdx.x * 128;   // pixel base (2 image rows)
    const int h0  = n0 >> 6;
    const int co0 = blockIdx.y * 128;
    const int b   = blockIdx.z;

    const __half* xp = g_xt + (size_t)b * NPIX * 256;

    float acc[2][8][4];
    #pragma unroll
    for (int mt = 0; mt < 2; mt++)
        #pragma unroll
        for (int nt = 0; nt < 8; nt++)
            #pragma unroll
            for (int k = 0; k < 4; k++) acc[mt][nt][k] = 0.f;

    unsigned a_rowoff[2];
    #pragma unroll
    for (int mt = 0; mt < 2; mt++) {
        int row = wm * 32 + mt * 16 + (lid & 7) + ((lid >> 3) & 1) * 8;
        a_rowoff[mt] = (unsigned)(row * 128) + ((unsigned)(lid >> 4)) * 16u;
    }
    int bn[4];
    #pragma unroll
    for (int j = 0; j < 4; j++) bn[j] = wn * 64 + j * 16 + (lid & 15);
    const unsigned bk8 = ((unsigned)(lid >> 4)) * 16u;

    auto stageA = [&](int tap, int ci0, int s) {
        unsigned dH = sb + OFF_A0 + (unsigned)s * A_BUF;
        #pragma unroll
        for (int i = tid; i < 1024; i += 256) {
            int cq = i & 7, row = i >> 3;
            size_t src = ((size_t)tap * 256 + co0 + row) * 256 + ci0 + cq * 8;
            cp16(dH + sw128((unsigned)(row * 128 + cq * 16)), g_wa + src);
        }
        cp_commit();
    };

    for (int cc = 0; cc < 4; cc++) {
        const int ci0 = cc << 6;
        __syncthreads();
        // ---- stage X patch (rows h0-1..h0+2, cols -1..64) ----
        for (int i = tid; i < 4 * 66 * 8; i += 256) {
            int cq  = i & 7;
            int row = i >> 3;
            int hl  = row / 66;
            int wv  = row - hl * 66;
            int h = h0 + hl - 1;
            int w = wv - 1;
            bool ok = ((unsigned)h < 64u) && ((unsigned)w < 64u);
            size_t src = ok ? (((size_t)(h * 64 + w)) * 256 + ci0 + cq * 8) : 0;
            cp16z(sb + OFF_X + sw128((unsigned)((hl * 68 + wv) * 128 + cq * 16)),
                  xp + src, ok);
        }
        stageA(0, ci0, 0);
        cp_wait0();
        __syncthreads();

        for (int tap = 0; tap < 9; tap++) {
            const int s  = tap & 1;
            const int dh = tap / 3 - 1;
            const int dw = tap % 3 - 1;
            if (tap < 8) stageA(tap + 1, ci0, s ^ 1);

            const unsigned AH = sb + OFF_A0 + (unsigned)s * A_BUF;

            unsigned b_rowoff[4];
            #pragma unroll
            for (int j = 0; j < 4; j++) {
                int hl = bn[j] >> 6, w = bn[j] & 63;
                b_rowoff[j] = (unsigned)(((hl + dh + 1) * 68 + (w + dw + 1)) * 128) + bk8;
            }

            #pragma unroll
            for (int ks = 0; ks < 4; ks++) {
                unsigned af[2][4], bf[4][4];
                #pragma unroll
                for (int mt = 0; mt < 2; mt++)
                    ldm_x4(af[mt], AH + sw128(a_rowoff[mt] + ks * 32u));
                #pragma unroll
                for (int j = 0; j < 4; j++)
                    ldm_x4(bf[j], sb + OFF_X + sw128(b_rowoff[j] + ks * 32u));
                #pragma unroll
                for (int mt = 0; mt < 2; mt++)
                    #pragma unroll
                    for (int nt = 0; nt < 8; nt++)
                        mma_f16(acc[mt][nt], af[mt],
                                bf[nt >> 1][nt & 1], bf[nt >> 1][(nt & 1) + 2]);
            }
            if (tap < 8) {
                cp_wait0();
                __syncthreads();
            }
        }
    }

    // ---- epilogue: store y as bf16 hi/lo pairs (arma input) ----
    const int r4 = lid >> 2, c2 = (lid & 3) << 1;
    #pragma unroll
    for (int mt = 0; mt < 2; mt++) {
        #pragma unroll
        for (int nt = 0; nt < 8; nt++) {
            int co  = co0 + wm * 32 + mt * 16 + r4;
            int pix = n0 + wn * 64 + nt * 8 + c2;
            size_t base = ((size_t)(b * 256 + co)) * NPIX + pix;
            unsigned uh, ul;
            split2(acc[mt][nt][0], acc[mt][nt][1], uh, ul);
            *(unsigned*)(g_yh + base) = uh;
            *(unsigned*)(g_yl + base) = ul;
            split2(acc[mt][nt][2], acc[mt][nt][3], uh, ul);
            *(unsigned*)(g_yh + base + (size_t)8 * NPIX) = uh;
            *(unsigned*)(g_yl + base + (size_t)8 * NPIX) = ul;
        }
    }
}

// ---------------- kernel 5: ARMA solve, 2 slices (same channel) per CTA ----------------
#define PA_BYH 0u
#define PA_BYL 32768u
#define PA_GYH 65536u
#define PA_GYL 73728u
#define PA_GXH 81920u
#define PA_GXL 90112u
#define ARMA_SMEM 98304

__global__ __launch_bounds__(128, 2)
void arma_mma_kernel(float* __restrict__ out) {
    extern __shared__ char smem[];
    const unsigned sb = smem_u32(smem);
    const int tid = threadIdx.x;
    const int lid = tid & 31;
    const int wid = tid >> 5;
    const int c   = blockIdx.x & 255;
    const int bg  = blockIdx.x >> 8;
    const int slice0 = (2 * bg) * 256 + c;

    for (int i = tid; i < 2048; i += 128) {
        int r = i >> 3, cq = i & 7;
        int s = r >> 6, h = r & 63;
        size_t e = ((size_t)(slice0 + s * 256)) * 4096 + h * 64 + cq * 8;
        unsigned swo = sw128((unsigned)(r * 128 + cq * 16));
        cp16(sb + PA_BYH + swo, g_yh + e);
        cp16(sb + PA_BYL + swo, g_yl + e);
    }
    for (int i = tid; i < 512; i += 128) {
        int r = i >> 3, cq = i & 7;
        size_t e = (size_t)c * 4096 + r * 64 + cq * 8;
        unsigned swo = sw128((unsigned)(r * 128 + cq * 16));
        cp16(sb + PA_GYH + swo, g_gyT_hi + e);
        cp16(sb + PA_GYL + swo, g_gyT_lo + e);
        cp16(sb + PA_GXH + swo, g_gx_hi  + e);
        cp16(sb + PA_GXL + swo, g_gx_lo  + e);
    }
    cp_commit(); cp_wait0();
    __syncthreads();

    const int wm = wid & 1, wn = wid >> 1;
    unsigned a_rowoff[2];
    #pragma unroll
    for (int mt = 0; mt < 2; mt++) {
        int row = wm * 32 + mt * 16 + (lid & 7) + ((lid >> 3) & 1) * 8;
        a_rowoff[mt] = (unsigned)(row * 128) + ((unsigned)(lid >> 4)) * 16u;
    }
    unsigned b_off[4];
    #pragma unroll
    for (int j = 0; j < 4; j++)
        b_off[j] = (unsigned)((wn * 64 + j * 16 + (lid & 15)) * 128)
                 + ((unsigned)(lid >> 4)) * 16u;
    const int r4 = lid >> 2, cp2 = (lid & 3) << 1;

    float acc[2][8][4];
    #pragma unroll
    for (int mt = 0; mt < 2; mt++)
        #pragma unroll
        for (int nt = 0; nt < 8; nt++)
            #pragma unroll
            for (int k = 0; k < 4; k++) acc[mt][nt][k] = 0.f;

    #pragma unroll
    for (int ks = 0; ks < 4; ks++) {
        unsigned AH[2][4], AL[2][4], BH[4][4], BL[4][4];
        #pragma unroll
        for (int mt = 0; mt < 2; mt++) {
            ldm_x4(AH[mt], sb + PA_GYH + sw128(a_rowoff[mt] + ks * 32u));
            ldm_x4(AL[mt], sb + PA_GYL + sw128(a_rowoff[mt] + ks * 32u));
        }
        #pragma unroll
        for (int j = 0; j < 4; j++) {
            ldm_x4(BH[j], sb + PA_BYH + sw128(b_off[j] + ks * 32u));
            ldm_x4(BL[j], sb + PA_BYL + sw128(b_off[j] + ks * 32u));
        }
        #pragma unroll
        for (int mt = 0; mt < 2; mt++)
            #pragma unroll
            for (int nt = 0; nt < 8; nt++) {
                unsigned h0b = BH[nt >> 1][nt & 1], h1b = BH[nt >> 1][(nt & 1) + 2];
                mma_bf16(acc[mt][nt], AH[mt], h0b, h1b);
                mma_bf16(acc[mt][nt], AH[mt],
                         BL[nt >> 1][nt & 1], BL[nt >> 1][(nt & 1) + 2]);
                mma_bf16(acc[mt][nt], AL[mt], h0b, h1b);
            }
    }
    __syncthreads();

    #pragma unroll
    for (int mt = 0; mt < 2; mt++) {
        #pragma unroll
        for (int nt = 0; nt < 8; nt++) {
            int m = wm * 32 + mt * 16 + r4;
            int n = wn * 64 + nt * 8 + cp2;
            int row = (n & ~63) + m;
            int col = n & 63;
            unsigned uh, ul;
            split2(acc[mt][nt][0], acc[mt][nt][1], uh, ul);
            unsigned ad = sw128((unsigned)(row * 128 + col * 2));
            *(unsigned*)(smem + PA_BYH + ad) = uh;
            *(unsigned*)(smem + PA_BYL + ad) = ul;
            split2(acc[mt][nt][2], acc[mt][nt][3], uh, ul);
            ad = sw128((unsigned)((row + 8) * 128 + col * 2));
            *(unsigned*)(smem + PA_BYH + ad) = uh;
            *(unsigned*)(smem + PA_BYL + ad) = ul;
        }
    }
    __syncthreads();

    float o[2][8][4];
    #pragma unroll
    for (int mt = 0; mt < 2; mt++)
        #pragma unroll
        for (int nt = 0; nt < 8; nt++)
            #pragma unroll
            for (int k = 0; k < 4; k++) o[mt][nt][k] = 0.f;

    #pragma unroll
    for (int ks = 0; ks < 4; ks++) {
        unsigned AH[2][4], AL[2][4], BH[4][4], BL[4][4];
        #pragma unroll
        for (int mt = 0; mt < 2; mt++) {
            ldm_x4(AH[mt], sb + PA_GXH + sw128(a_rowoff[mt] + ks * 32u));
            ldm_x4(AL[mt], sb + PA_GXL + sw128(a_rowoff[mt] + ks * 32u));
        }
        #pragma unroll
        for (int j = 0; j < 4; j++) {
            ldm_x4(BH[j], sb + PA_BYH + sw128(b_off[j] + ks * 32u));
            ldm_x4(BL[j], sb + PA_BYL + sw128(b_off[j] + ks * 32u));
        }
        #pragma unroll
        for (int mt = 0; mt < 2; mt++)
            #pragma unroll
            for (int nt = 0; nt < 8; nt++) {
                unsigned h0b = BH[nt >> 1][nt & 1], h1b = BH[nt >> 1][(nt & 1) + 2];
                mma_bf16(o[mt][nt], AH[mt], h0b, h1b);
                mma_bf16(o[mt][nt], AH[mt],
                         BL[nt >> 1][nt & 1], BL[nt >> 1][(nt & 1) + 2]);
                mma_bf16(o[mt][nt], AL[mt], h0b, h1b);
            }
    }

    #pragma unroll
    for (int mt = 0; mt < 2; mt++) {
        #pragma unroll
        for (int nt = 0; nt < 8; nt++) {
            int m = wm * 32 + mt * 16 + r4;
            int n = wn * 64 + nt * 8 + cp2;
            int s = n >> 6;
            int j = n & 63;
            float* O = out + ((size_t)(slice0 + s * 256)) * 4096;
            *(float2*)(O + m * 64 + j)       = make_float2(o[mt][nt][0], o[mt][nt][1]);
            *(float2*)(O + (m + 8) * 64 + j) = make_float2(o[mt][nt][2], o[mt][nt][3]);
        }
    }
}

// ---------------- launcher ----------------
extern "C" void kernel_launch(void* const* d_in, const int* in_sizes, int n_in,
                              void* d_out, int out_size) {
    const float* x     = (const float*)d_in[0];
    const float* w     = (const float*)d_in[1];
    const float* alpha = (const float*)d_in[2];
    float* out = (float*)d_out;

    cudaFuncSetAttribute(conv_mma_kernel,
                         cudaFuncAttributeMaxDynamicSharedMemorySize, CONV_SMEM);
    cudaFuncSetAttribute(arma_mma_kernel,
                         cudaFuncAttributeMaxDynamicSharedMemorySize, ARMA_SMEM);

    wa_kernel<<<CCH, 256>>>(w);
    ginv_kernel<<<CCH, 128>>>(alpha);
    gmat_kernel<<<CCH, 256>>>();
    xt_kernel<<<dim3(64, 4, 32), 256>>>(x);
    conv_mma_kernel<<<dim3(32, 2, 32), 256, CONV_SMEM>>>();
    arma_mma_kernel<<<16 * 256, 128, ARMA_SMEM>>>(out);
}

// round 11
// speedup vs baseline: 1.9548x; 1.1175x over previous
#include <cuda_runtime.h>
#include <cuda_bf16.h>
#include <cuda_fp16.h>
#include <math.h>

// ---------------- problem constants ----------------
#define BSZ   32
#define CCH   256
#define NPIX  4096      // 64x64

// ---------------- scratch (device globals; no allocation) ----------------
__device__ __align__(16) __half  g_yt[(size_t)BSZ * CCH * NPIX];   // conv out fp16
__device__ __align__(16) __half  g_xt[(size_t)BSZ * NPIX * CCH];   // x transposed fp16
__device__ __align__(16) __half  g_wa[9 * CCH * CCH];              // weights fp16
__device__ float                 g_ginv[2 * CCH * 64];
__device__ __align__(16) __half  g_gyT[CCH * 4096];                // GyT[c][j][q] fp16
__device__ __align__(16) __half  g_gx[CCH * 4096];                 // Gx[c][i][h] fp16

// ---------------- helpers ----------------
__device__ __forceinline__ unsigned smem_u32(const void* p) {
    unsigned r;
    asm("{ .reg .u64 t; cvta.to.shared.u64 t, %1; cvt.u32.u64 %0, t; }" : "=r"(r) : "l"(p));
    return r;
}
__device__ __forceinline__ unsigned sw128(unsigned off) { return off ^ ((off >> 3) & 0x70); }

__device__ __forceinline__ void ldm_x4(unsigned* r, unsigned addr) {
    asm volatile("ldmatrix.sync.aligned.m8n8.x4.shared.b16 {%0,%1,%2,%3}, [%4];"
        : "=r"(r[0]), "=r"(r[1]), "=r"(r[2]), "=r"(r[3]) : "r"(addr));
}
__device__ __forceinline__ void mma_f16(float* d, const unsigned* a,
                                        unsigned b0, unsigned b1) {
    asm volatile("mma.sync.aligned.m16n8k16.row.col.f32.f16.f16.f32 "
        "{%0,%1,%2,%3}, {%4,%5,%6,%7}, {%8,%9}, {%0,%1,%2,%3};"
        : "+f"(d[0]), "+f"(d[1]), "+f"(d[2]), "+f"(d[3])
        : "r"(a[0]), "r"(a[1]), "r"(a[2]), "r"(a[3]), "r"(b0), "r"(b1));
}
__device__ __forceinline__ void cp16(unsigned dst, const void* src) {
    asm volatile("cp.async.cg.shared.global [%0], [%1], 16;" :: "r"(dst), "l"(src));
}
__device__ __forceinline__ void cp16z(unsigned dst, const void* src, bool ok) {
    int sz = ok ? 16 : 0;
    asm volatile("cp.async.cg.shared.global [%0], [%1], 16, %2;"
                 :: "r"(dst), "l"(src), "r"(sz));
}
__device__ __forceinline__ void cp_commit() {
    asm volatile("cp.async.commit_group;" ::: "memory");
}
__device__ __forceinline__ void cp_wait0() {
    asm volatile("cp.async.wait_group 0;" ::: "memory");
}
// pack two floats into fp16x2 word
__device__ __forceinline__ unsigned pk_h2(float a, float b) {
    __half ha = __float2half_rn(a), hb = __float2half_rn(b);
    return (unsigned)__half_as_ushort(ha) | ((unsigned)__half_as_ushort(hb) << 16);
}

// ---------------- kernel 1: weights -> [tap][co][ci] fp16 ----------------
__global__ void wa_kernel(const float* __restrict__ w) {
    __shared__ float s[2304];
    const int co  = blockIdx.x;
    const int tid = threadIdx.x;
    for (int i = tid; i < 2304; i += 256) s[i] = w[(size_t)co * 2304 + i];
    __syncthreads();
    for (int it = tid; it < 288; it += 256) {   // 9 taps x 32 ci-groups
        int tap = it >> 5, grp = it & 31;
        unsigned h4[4];
        #pragma unroll
        for (int k = 0; k < 4; k++)
            h4[k] = pk_h2(s[(grp * 8 + k * 2) * 9 + tap],
                          s[(grp * 8 + k * 2 + 1) * 9 + tap]);
        size_t o = ((size_t)tap * 256 + co) * 256 + grp * 8;
        *(uint4*)(g_wa + o) = make_uint4(h4[0], h4[1], h4[2], h4[3]);
    }
}

// ---------------- kernel 2: x -> transposed fp16 ----------------
__global__ void xt_kernel(const float* __restrict__ x) {
    __shared__ float s[64][65];
    int p0  = blockIdx.x * 64;
    int ci0 = blockIdx.y * 64;
    int b   = blockIdx.z;
    int tid = threadIdx.x;
    for (int i = tid; i < 1024; i += 256) {     // float4 loads
        int ci = i >> 4, p4 = (i & 15) << 2;
        float4 v = *(const float4*)(x + ((size_t)(b * 256 + ci0 + ci)) * NPIX + p0 + p4);
        s[ci][p4 + 0] = v.x; s[ci][p4 + 1] = v.y;
        s[ci][p4 + 2] = v.z; s[ci][p4 + 3] = v.w;
    }
    __syncthreads();
    for (int i = tid; i < 512; i += 256) {      // 64 pix x 8 ci-groups
        int pix = i >> 3, grp = i & 7;
        unsigned h4[4];
        #pragma unroll
        for (int k = 0; k < 4; k++)
            h4[k] = pk_h2(s[grp * 8 + k * 2][pix], s[grp * 8 + k * 2 + 1][pix]);
        size_t o = ((size_t)b * NPIX + p0 + pix) * 256 + ci0 + grp * 8;
        *(uint4*)(g_xt + o) = make_uint4(h4[0], h4[1], h4[2], h4[3]);
    }
}

// ---------------- kernel 3: circulant inverse kernels ----------------
__global__ void ginv_kernel(const float* __restrict__ alpha) {
    int c = blockIdx.x;
    int t = threadIdx.x;
    int dir = t >> 6;
    int n   = t & 63;
    float t00 = tanhf(alpha[c*4+0]), t01 = tanhf(alpha[c*4+1]);
    float t10 = tanhf(alpha[c*4+2]), t11 = tanhf(alpha[c*4+3]);
    const float R = 0.70710678118654752440f;
    float a0, a2;
    if (dir == 0) { a0 = (t00 + t01) * R; a2 = (t01 - t00) * R; }
    else          { a0 = (t10 + t11) * R; a2 = (t11 - t10) * R; }
    double ar = (double)a0 + (double)a2;
    double ai = (double)a0 - (double)a2;
    double s = 0.0;
    for (int u = 0; u < 64; u++) {
        double th  = (2.0 * 3.14159265358979323846 / 64.0) * (double)u;
        double Fre = 1.0 + ar * cos(th);
        double Fim = ai * sin(th);
        double den = Fre * Fre + Fim * Fim;
        double ang = th * (double)n;
        s += (cos(ang) * Fre + sin(ang) * Fim) / den;
    }
    g_ginv[(dir * CCH + c) * 64 + n] = (float)(s / 64.0);
}

// ---------------- kernel 3b: circulant matrices (fp16) ----------------
__global__ void gmat_kernel() {
    int c   = blockIdx.x;
    int tid = threadIdx.x;
    __shared__ float gx[64], gy[64];
    if (tid < 64)                 gx[tid]      = g_ginv[c * 64 + tid];
    else if (tid < 128)           gy[tid - 64] = g_ginv[(CCH + c) * 64 + (tid - 64)];
    __syncthreads();
    for (int i = tid; i < 512; i += 256) {      // 64 rows x 8 q-groups
        int r = i >> 3, grp = i & 7;
        unsigned x4[4], y4[4];
        #pragma unroll
        for (int k = 0; k < 4; k++) {
            int q0 = grp * 8 + k * 2;
            x4[k] = pk_h2(gx[(r - q0) & 63], gx[(r - q0 - 1) & 63]);
            y4[k] = pk_h2(gy[(r - q0) & 63], gy[(r - q0 - 1) & 63]);
        }
        size_t o = (size_t)c * 4096 + r * 64 + grp * 8;
        *(uint4*)(g_gx  + o) = make_uint4(x4[0], x4[1], x4[2], x4[3]);
        *(uint4*)(g_gyT + o) = make_uint4(y4[0], y4[1], y4[2], y4[3]);
    }
}

// ---------------- kernel 4: implicit-GEMM conv, single-term fp16 ----------------
// CTA: M=128 co x N=128 pixels. 256 threads = 8 warps (4M x 2N), warp tile 32x64.
#define XP_ROWS  (4 * 68)
#define XP_BYTES (XP_ROWS * 128)       // 34816
#define OFF_X  0u
#define OFF_A0 34816u
#define A_BUF  16384u
#define CONV_SMEM (OFF_A0 + 2 * A_BUF) // 67584

__global__ __launch_bounds__(256, 2)
void conv_mma_kernel() {
    extern __shared__ char smem[];
    const unsigned sb = smem_u32(smem);
    const int tid = threadIdx.x;
    const int lid = tid & 31;
    const int wid = tid >> 5;
    const int wm  = wid & 3;            // 0..3 (32 co each)
    const int wn  = wid >> 2;           // 0..1 (64 pixels each)

    const int n0  = blockIdx.x * 128;   // pixel base (2 image rows)
    const int h0  = n0 >> 6;
    const int co0 = blockIdx.y * 128;
    const int b   = blockIdx.z;

    const __half* xp = g_xt + (size_t)b * NPIX * 256;

    float acc[2][8][4];
    #pragma unroll
    for (int mt = 0; mt < 2; mt++)
        #pragma unroll
        for (int nt = 0; nt < 8; nt++)
            #pragma unroll
            for (int k = 0; k < 4; k++) acc[mt][nt][k] = 0.f;

    unsigned a_rowoff[2];
    #pragma unroll
    for (int mt = 0; mt < 2; mt++) {
        int row = wm * 32 + mt * 16 + (lid & 7) + ((lid >> 3) & 1) * 8;
        a_rowoff[mt] = (unsigned)(row * 128) + ((unsigned)(lid >> 4)) * 16u;
    }
    int bn[4];
    #pragma unroll
    for (int j = 0; j < 4; j++) bn[j] = wn * 64 + j * 16 + (lid & 15);
    const unsigned bk8 = ((unsigned)(lid >> 4)) * 16u;

    auto stageA = [&](int tap, int ci0, int s) {
        unsigned dH = sb + OFF_A0 + (unsigned)s * A_BUF;
        #pragma unroll
        for (int i = tid; i < 1024; i += 256) {
            int cq = i & 7, row = i >> 3;
            size_t src = ((size_t)tap * 256 + co0 + row) * 256 + ci0 + cq * 8;
            cp16(dH + sw128((unsigned)(row * 128 + cq * 16)), g_wa + src);
        }
        cp_commit();
    };

    for (int cc = 0; cc < 4; cc++) {
        const int ci0 = cc << 6;
        __syncthreads();
        for (int i = tid; i < 4 * 66 * 8; i += 256) {
            int cq  = i & 7;
            int row = i >> 3;
            int hl  = row / 66;
            int wv  = row - hl * 66;
            int h = h0 + hl - 1;
            int w = wv - 1;
            bool ok = ((unsigned)h < 64u) && ((unsigned)w < 64u);
            size_t src = ok ? (((size_t)(h * 64 + w)) * 256 + ci0 + cq * 8) : 0;
            cp16z(sb + OFF_X + sw128((unsigned)((hl * 68 + wv) * 128 + cq * 16)),
                  xp + src, ok);
        }
        stageA(0, ci0, 0);
        cp_wait0();
        __syncthreads();

        for (int tap = 0; tap < 9; tap++) {
            const int s  = tap & 1;
            const int dh = tap / 3 - 1;
            const int dw = tap % 3 - 1;
            if (tap < 8) stageA(tap + 1, ci0, s ^ 1);

            const unsigned AH = sb + OFF_A0 + (unsigned)s * A_BUF;

            unsigned b_rowoff[4];
            #pragma unroll
            for (int j = 0; j < 4; j++) {
                int hl = bn[j] >> 6, w = bn[j] & 63;
                b_rowoff[j] = (unsigned)(((hl + dh + 1) * 68 + (w + dw + 1)) * 128) + bk8;
            }

            #pragma unroll
            for (int ks = 0; ks < 4; ks++) {
                unsigned af[2][4], bf[4][4];
                #pragma unroll
                for (int mt = 0; mt < 2; mt++)
                    ldm_x4(af[mt], AH + sw128(a_rowoff[mt] + ks * 32u));
                #pragma unroll
                for (int j = 0; j < 4; j++)
                    ldm_x4(bf[j], sb + OFF_X + sw128(b_rowoff[j] + ks * 32u));
                #pragma unroll
                for (int mt = 0; mt < 2; mt++)
                    #pragma unroll
                    for (int nt = 0; nt < 8; nt++)
                        mma_f16(acc[mt][nt], af[mt],
                                bf[nt >> 1][nt & 1], bf[nt >> 1][(nt & 1) + 2]);
            }
            if (tap < 8) {
                cp_wait0();
                __syncthreads();
            }
        }
    }

    // ---- epilogue: store y as fp16 ----
    const int r4 = lid >> 2, c2 = (lid & 3) << 1;
    #pragma unroll
    for (int mt = 0; mt < 2; mt++) {
        #pragma unroll
        for (int nt = 0; nt < 8; nt++) {
            int co  = co0 + wm * 32 + mt * 16 + r4;
            int pix = n0 + wn * 64 + nt * 8 + c2;
            size_t base = ((size_t)(b * 256 + co)) * NPIX + pix;
            *(unsigned*)(g_yt + base) = pk_h2(acc[mt][nt][0], acc[mt][nt][1]);
            *(unsigned*)(g_yt + base + (size_t)8 * NPIX) =
                pk_h2(acc[mt][nt][2], acc[mt][nt][3]);
        }
    }
}

// ---------------- kernel 5: ARMA solve, single-term fp16, 2 slices/CTA ----------------
// stage 1: UT[s*64+j][h] = sum_q GyT[j][q] * Y_s[h][q]
// stage 2: out_s[i][j]   = sum_h Gx[i][h]  * UT[s*64+j][h]
// 32 KB smem -> 4 CTAs/SM. UT overwrites Y region.
#define PA_Y  0u
#define PA_GY 16384u
#define PA_GX 24576u
#define ARMA_SMEM 32768

__global__ __launch_bounds__(128, 4)
void arma_mma_kernel(float* __restrict__ out) {
    extern __shared__ char smem[];
    const unsigned sb = smem_u32(smem);
    const int tid = threadIdx.x;
    const int lid = tid & 31;
    const int wid = tid >> 5;
    const int c   = blockIdx.x & 255;
    const int bg  = blockIdx.x >> 8;
    const int slice0 = (2 * bg) * 256 + c;

    // stage inputs: Y (2 slices, 128 rows x 128B), G matrices (64 rows x 128B each)
    for (int i = tid; i < 1024; i += 128) {
        int r = i >> 3, cq = i & 7;
        int s = r >> 6, h = r & 63;
        size_t e = ((size_t)(slice0 + s * 256)) * 4096 + h * 64 + cq * 8;
        cp16(sb + PA_Y + sw128((unsigned)(r * 128 + cq * 16)), g_yt + e);
    }
    for (int i = tid; i < 512; i += 128) {
        int r = i >> 3, cq = i & 7;
        size_t e = (size_t)c * 4096 + r * 64 + cq * 8;
        unsigned swo = sw128((unsigned)(r * 128 + cq * 16));
        cp16(sb + PA_GY + swo, g_gyT + e);
        cp16(sb + PA_GX + swo, g_gx  + e);
    }
    cp_commit(); cp_wait0();
    __syncthreads();

    // warp layout: 4 warps = 2M x 2N; warp tile M=32 (mt=2), N=64 (nt=8)
    const int wm = wid & 1, wn = wid >> 1;
    unsigned a_rowoff[2];
    #pragma unroll
    for (int mt = 0; mt < 2; mt++) {
        int row = wm * 32 + mt * 16 + (lid & 7) + ((lid >> 3) & 1) * 8;
        a_rowoff[mt] = (unsigned)(row * 128) + ((unsigned)(lid >> 4)) * 16u;
    }
    unsigned b_off[4];
    #pragma unroll
    for (int j = 0; j < 4; j++)
        b_off[j] = (unsigned)((wn * 64 + j * 16 + (lid & 15)) * 128)
                 + ((unsigned)(lid >> 4)) * 16u;
    const int r4 = lid >> 2, cp2 = (lid & 3) << 1;

    // ---- stage 1 ----
    float acc[2][8][4];
    #pragma unroll
    for (int mt = 0; mt < 2; mt++)
        #pragma unroll
        for (int nt = 0; nt < 8; nt++)
            #pragma unroll
            for (int k = 0; k < 4; k++) acc[mt][nt][k] = 0.f;

    #pragma unroll
    for (int ks = 0; ks < 4; ks++) {
        unsigned A[2][4], B[4][4];
        #pragma unroll
        for (int mt = 0; mt < 2; mt++)
            ldm_x4(A[mt], sb + PA_GY + sw128(a_rowoff[mt] + ks * 32u));
        #pragma unroll
        for (int j = 0; j < 4; j++)
            ldm_x4(B[j], sb + PA_Y + sw128(b_off[j] + ks * 32u));
        #pragma unroll
        for (int mt = 0; mt < 2; mt++)
            #pragma unroll
            for (int nt = 0; nt < 8; nt++)
                mma_f16(acc[mt][nt], A[mt],
                        B[nt >> 1][nt & 1], B[nt >> 1][(nt & 1) + 2]);
    }
    __syncthreads();   // all Y reads complete before overwrite

    // write UT (row = s*64 + j, col = h) into Y region as fp16
    #pragma unroll
    for (int mt = 0; mt < 2; mt++) {
        #pragma unroll
        for (int nt = 0; nt < 8; nt++) {
            int m = wm * 32 + mt * 16 + r4;
            int n = wn * 64 + nt * 8 + cp2;
            int row = (n & ~63) + m;
            int col = n & 63;
            *(unsigned*)(smem + PA_Y + sw128((unsigned)(row * 128 + col * 2))) =
                pk_h2(acc[mt][nt][0], acc[mt][nt][1]);
            *(unsigned*)(smem + PA_Y + sw128((unsigned)((row + 8) * 128 + col * 2))) =
                pk_h2(acc[mt][nt][2], acc[mt][nt][3]);
        }
    }
    __syncthreads();

    // ---- stage 2 ----
    float o[2][8][4];
    #pragma unroll
    for (int mt = 0; mt < 2; mt++)
        #pragma unroll
        for (int nt = 0; nt < 8; nt++)
            #pragma unroll
            for (int k = 0; k < 4; k++) o[mt][nt][k] = 0.f;

    #pragma unroll
    for (int ks = 0; ks < 4; ks++) {
        unsigned A[2][4], B[4][4];
        #pragma unroll
        for (int mt = 0; mt < 2; mt++)
            ldm_x4(A[mt], sb + PA_GX + sw128(a_rowoff[mt] + ks * 32u));
        #pragma unroll
        for (int j = 0; j < 4; j++)
            ldm_x4(B[j], sb + PA_Y + sw128(b_off[j] + ks * 32u));
        #pragma unroll
        for (int mt = 0; mt < 2; mt++)
            #pragma unroll
            for (int nt = 0; nt < 8; nt++)
                mma_f16(o[mt][nt], A[mt],
                        B[nt >> 1][nt & 1], B[nt >> 1][(nt & 1) + 2]);
    }

    // epilogue: out_s[i][j]; fragment (m=i, n=s*64+j)
    #pragma unroll
    for (int mt = 0; mt < 2; mt++) {
        #pragma unroll
        for (int nt = 0; nt < 8; nt++) {
            int m = wm * 32 + mt * 16 + r4;
            int n = wn * 64 + nt * 8 + cp2;
            int s = n >> 6;
            int j = n & 63;
            float* O = out + ((size_t)(slice0 + s * 256)) * 4096;
            *(float2*)(O + m * 64 + j)       = make_float2(o[mt][nt][0], o[mt][nt][1]);
            *(float2*)(O + (m + 8) * 64 + j) = make_float2(o[mt][nt][2], o[mt][nt][3]);
        }
    }
}

// ---------------- launcher ----------------
extern "C" void kernel_launch(void* const* d_in, const int* in_sizes, int n_in,
                              void* d_out, int out_size) {
    const float* x     = (const float*)d_in[0];
    const float* w     = (const float*)d_in[1];
    const float* alpha = (const float*)d_in[2];
    float* out = (float*)d_out;

    cudaFuncSetAttribute(conv_mma_kernel,
                         cudaFuncAttributeMaxDynamicSharedMemorySize, CONV_SMEM);
    cudaFuncSetAttribute(arma_mma_kernel,
                         cudaFuncAttributeMaxDynamicSharedMemorySize, ARMA_SMEM);

    wa_kernel<<<CCH, 256>>>(w);
    ginv_kernel<<<CCH, 128>>>(alpha);
    gmat_kernel<<<CCH, 256>>>();
    xt_kernel<<<dim3(64, 4, 32), 256>>>(x);
    conv_mma_kernel<<<dim3(32, 2, 32), 256, CONV_SMEM>>>();
    arma_mma_kernel<<<16 * 256, 128, ARMA_SMEM>>>(out);
}